// round 13
// baseline (speedup 1.0000x reference)
#include <cuda_runtime.h>
#include <cuda_bf16.h>
#include <math.h>

typedef unsigned long long u64;
typedef unsigned int u32;

#define Nn 100000
#define Ee 1600000
#define Ff 128
#define NFf 4
#define Dd 64
#define NLl 3
#define Gg 128
#define NTILE 782   // ceil(Nn/128)

// ---------------- device scratch (no allocations allowed) ----------------
__device__ int   g_deg[Nn];
__device__ int   g_rowptr[Nn + 1];
__device__ int   g_fill[Nn];
__device__ int   g_bsums[256];
__device__ int   g_srcs[Ee];
__device__ int   g_eids[Ee];
__device__ float g_wcsr[NFf * Ee];
__device__ float g_stateA[NFf * Nn * Dd];
__device__ float g_stateB[NFf * Nn * Dd];
__device__ int   g_gcnt[Gg];
__device__ int   g_gstart[Gg + 1];
// fragment-packed bf16 weights, j-pair interleaved (uint4 = 2 fragments)
__device__ uint2 g_pkconv[12 * 4096];   // [wl][mat:relH,relL,rootH,rootL][ks4][pair4][lane32][2]
__device__ uint2 g_pkgru[4 * 12288];    // [f][ihH,ihL,hhH,hhL (2048 ea), inH,inL,hnH,hnL (1024 ea)]

// ---------------- helpers ----------------
__device__ __forceinline__ u64 ffma2(u64 a, u64 b, u64 c) {
    u64 d; asm("fma.rn.f32x2 %0,%1,%2,%3;" : "=l"(d) : "l"(a), "l"(b), "l"(c)); return d;
}
__device__ __forceinline__ u64 splat2(float v) {
    u64 d; u32 r = __float_as_uint(v);
    asm("mov.b64 %0,{%1,%2};" : "=l"(d) : "r"(r), "r"(r)); return d;
}
__device__ __forceinline__ float2 unpk(u64 v) {
    u32 lo, hi; asm("mov.b64 {%0,%1},%2;" : "=r"(lo), "=r"(hi) : "l"(v));
    return make_float2(__uint_as_float(lo), __uint_as_float(hi));
}
__device__ __forceinline__ float sigm(float v) { return 1.f / (1.f + __expf(-v)); }
__device__ __forceinline__ float tanh_f(float v) { return 2.f / (1.f + __expf(-2.f * v)) - 1.f; }

__device__ __forceinline__ u32 smem_u32(const void* p) {
    u32 a;
    asm("{ .reg .u64 t; cvta.to.shared.u64 t, %1; cvt.u32.u64 %0, t; }" : "=r"(a) : "l"(p));
    return a;
}

__device__ __forceinline__ void split2(float a0, float a1, u32& hi, u32& lo) {
    __nv_bfloat16 h0 = __float2bfloat16(a0), h1 = __float2bfloat16(a1);
    __nv_bfloat162 hp = __halves2bfloat162(h0, h1);
    float r0 = a0 - __bfloat162float(h0);
    float r1 = a1 - __bfloat162float(h1);
    __nv_bfloat162 lp = __floats2bfloat162_rn(r0, r1);
    hi = *(u32*)&hp; lo = *(u32*)&lp;
}

__device__ __forceinline__ u32 pkbf(float a, float b, bool lo) {
    __nv_bfloat16 ah = __float2bfloat16(a), bh = __float2bfloat16(b);
    if (lo) {
        ah = __float2bfloat16(a - __bfloat162float(ah));
        bh = __float2bfloat16(b - __bfloat162float(bh));
    }
    __nv_bfloat162 p = __halves2bfloat162(ah, bh);
    return *(u32*)&p;
}

__device__ __forceinline__ uint4 ldm(u32 addr) {
    uint4 r;
    asm volatile("ldmatrix.sync.aligned.m8n8.x4.shared.b16 {%0,%1,%2,%3}, [%4];"
        : "=r"(r.x), "=r"(r.y), "=r"(r.z), "=r"(r.w) : "r"(addr));
    return r;
}
__device__ __forceinline__ void mmaf(float d[4], uint4 a, uint2 b) {
    asm volatile("mma.sync.aligned.m16n8k16.row.col.f32.bf16.bf16.f32 "
        "{%0,%1,%2,%3}, {%4,%5,%6,%7}, {%8,%9}, {%0,%1,%2,%3};"
        : "+f"(d[0]), "+f"(d[1]), "+f"(d[2]), "+f"(d[3])
        : "r"(a.x), "r"(a.y), "r"(a.z), "r"(a.w), "r"(b.x), "r"(b.y));
}

// ---------------- CSR build ----------------
__global__ void k_zero() {
    int i = blockIdx.x * blockDim.x + threadIdx.x;
    if (i < Nn) g_deg[i] = 0;
    if (i < Gg) g_gcnt[i] = 0;
}

__global__ void k_hist(const int* __restrict__ dst, const int* __restrict__ batch) {
    int i = blockIdx.x * blockDim.x + threadIdx.x;
    if (i < Ee) atomicAdd(&g_deg[dst[i]], 1);
    if (i < Nn) atomicAdd(&g_gcnt[batch[i]], 1);
}

__global__ void k_scan1() {
    __shared__ int tmp[1024];
    int i = blockIdx.x * 1024 + threadIdx.x;
    int v = (i < Nn) ? g_deg[i] : 0;
    tmp[threadIdx.x] = v;
    __syncthreads();
    for (int off = 1; off < 1024; off <<= 1) {
        int t = 0;
        if (threadIdx.x >= off) t = tmp[threadIdx.x - off];
        __syncthreads();
        if (threadIdx.x >= off) tmp[threadIdx.x] += t;
        __syncthreads();
    }
    if (i < Nn) g_rowptr[i + 1] = tmp[threadIdx.x];
    if (threadIdx.x == 1023) g_bsums[blockIdx.x] = tmp[1023];
}

__global__ void k_scan2(int nb) {
    if (threadIdx.x == 0 && blockIdx.x == 0) {
        int run = 0;
        for (int b = 0; b < nb; b++) { int v = g_bsums[b]; g_bsums[b] = run; run += v; }
    }
}

__global__ void k_scan3() {
    int i = blockIdx.x * 1024 + threadIdx.x;
    if (i < Nn) {
        int v = g_rowptr[i + 1] + g_bsums[blockIdx.x];
        g_rowptr[i + 1] = v;
        if (i + 1 < Nn) g_fill[i + 1] = v;
    }
    if (i == 0) { g_rowptr[0] = 0; g_fill[0] = 0; }
}

__global__ void k_scatter(const int* __restrict__ src, const int* __restrict__ dst) {
    int e = blockIdx.x * blockDim.x + threadIdx.x;
    if (e < Ee) {
        int d = dst[e];
        int p = atomicAdd(&g_fill[d], 1);
        g_srcs[p] = src[e];
        g_eids[p] = e;
    }
}

__global__ void k_sortseg() {
    int n = blockIdx.x * blockDim.x + threadIdx.x;
    if (n >= Nn) return;
    int b = g_rowptr[n], e = g_rowptr[n + 1];
    for (int i = b + 1; i < e; i++) {
        int ke = g_eids[i], ks = g_srcs[i];
        int j = i - 1;
        while (j >= b && g_eids[j] > ke) {
            g_eids[j + 1] = g_eids[j];
            g_srcs[j + 1] = g_srcs[j];
            j--;
        }
        g_eids[j + 1] = ke;
        g_srcs[j + 1] = ks;
    }
}

__global__ void k_buildw(const float* __restrict__ att) {
    int j = blockIdx.x * blockDim.x + threadIdx.x;
    if (j < Ee) {
        int e = g_eids[j];
#pragma unroll
        for (int f = 0; f < NFf; f++) g_wcsr[f * Ee + j] = att[f * Ee + e];
    }
}

__global__ void k_gscan() {
    if (threadIdx.x == 0 && blockIdx.x == 0) {
        int run = 0;
        for (int g = 0; g < Gg; g++) { g_gstart[g] = run; run += g_gcnt[g]; }
        g_gstart[Gg] = run;
    }
}

// ---------------- weight pre-pack: bf16 hi/lo fragments, j-pair interleaved ----------------
// frag for (ks,nt): lane l holds {B[k0+2s][n],B[k0+2s+1][n]},{B[k0+8+2s][n],B[k0+9+2s][n]}
// s=l&3, n=nt*8+(l>>2), k0=ks*16. Pair layout: uint2 dst offset within mat block =
//   (ks*NPAIR + (nt>>1))*64 + lane*2 + (nt&1)   so a uint4 load yields frags for nt=2p, 2p+1.
__global__ void k_pack(const float* __restrict__ Wrel, const float* __restrict__ Wroot,
                       const float* __restrict__ Wih, const float* __restrict__ Whh) {
    int i = blockIdx.x * blockDim.x + threadIdx.x;
    if (i >= 98304) return;
    float v00, v01, v10, v11;
    bool lo;
    uint2* dst;
    if (i < 49152) {
        int wl = i >> 12;
        int r = i & 4095;
        int mat = r >> 10;          // 0 relH, 1 relL, 2 rootH, 3 rootL
        int fr = r & 1023;
        int ks = fr >> 8, nt = (fr >> 5) & 7, lane = fr & 31;
        int s = lane & 3, n = nt * 8 + (lane >> 2);
        int k0 = ks * 16 + 2 * s;
        const float* Wm = ((mat >= 2) ? Wroot : Wrel) + wl * 4096;  // B[k][n] = W[k*64+n]
        v00 = Wm[k0 * 64 + n];       v01 = Wm[(k0 + 1) * 64 + n];
        v10 = Wm[(k0 + 8) * 64 + n]; v11 = Wm[(k0 + 9) * 64 + n];
        lo = (mat & 1);
        int off = (ks * 4 + (nt >> 1)) * 64 + lane * 2 + (nt & 1);
        dst = g_pkconv + wl * 4096 + mat * 1024 + off;
    } else {
        int j = i - 49152;
        int f = j / 12288;
        int r = j % 12288;
        const float* WI = Wih + f * 12288;
        const float* WH = Whh + f * 12288;
        if (r < 8192) {             // rz: ihH, ihL, hhH, hhL (2048 uint2 each)
            int mat = r >> 11;
            int fr = r & 2047;
            int ks = fr >> 9, nt = (fr >> 5) & 15, lane = fr & 31;
            int s = lane & 3, n = nt * 8 + (lane >> 2);
            int k0 = ks * 16 + 2 * s;
            const float* Wm = (mat >= 2) ? WH : WI;        // B[k][n] = W[n*64+k]
            v00 = Wm[n * 64 + k0];     v01 = Wm[n * 64 + k0 + 1];
            v10 = Wm[n * 64 + k0 + 8]; v11 = Wm[n * 64 + k0 + 9];
            lo = (mat & 1);
            int off = (ks * 8 + (nt >> 1)) * 64 + lane * 2 + (nt & 1);
            dst = g_pkgru + f * 12288 + mat * 2048 + off;
        } else {                    // n gate: inH, inL, hnH, hnL (1024 uint2 each)
            int rn = r - 8192;
            int mat = rn >> 10;
            int fr = rn & 1023;
            int ks = fr >> 8, nt = (fr >> 5) & 7, lane = fr & 31;
            int s = lane & 3, n = nt * 8 + (lane >> 2);
            int k0 = ks * 16 + 2 * s;
            const float* Wm = (mat >= 2) ? WH : WI;        // B[k][n] = W[(128+n)*64+k]
            v00 = Wm[(128 + n) * 64 + k0];     v01 = Wm[(128 + n) * 64 + k0 + 1];
            v10 = Wm[(128 + n) * 64 + k0 + 8]; v11 = Wm[(128 + n) * 64 + k0 + 9];
            lo = (mat & 1);
            int off = (ks * 4 + (nt >> 1)) * 64 + lane * 2 + (nt & 1);
            dst = g_pkgru + f * 12288 + 8192 + mat * 1024 + off;
        }
    }
    *dst = make_uint2(pkbf(v00, v01, lo), pkbf(v10, v11, lo));
}

// ---------------- lin (FFMA champion, unchanged) ----------------
#define LIN_SHM ((8192 + 64 + 16 * 1280) * 4)
__global__ __launch_bounds__(512, 1) void k_lin(const float* __restrict__ x,
                                                const float* __restrict__ W_all,
                                                const float* __restrict__ b_all,
                                                float* __restrict__ out_base) {
    extern __shared__ float sh[];
    float* sW = sh;
    float* sb = sW + 8192;
    float* sX = sb + 64;
    int f = blockIdx.x & 3;
    int fslot = blockIdx.x >> 2;
    int nslot = gridDim.x >> 2;
    const float* W = W_all + f * Ff * Dd;
    const float* b = b_all + f * Dd;
    float* out = out_base + f * Nn * Dd;

    int tid = threadIdx.x;
    for (int i = tid; i < 8192; i += 512) sW[i] = W[i];
    if (tid < 64) sb[tid] = b[tid];
    __syncthreads();
    int warp = tid >> 5, lane = tid & 31;
    int d0 = 2 * lane;
    int nt = lane >> 2, cg = lane & 3;
    float* sXw = sX + warp * 1280;
    float bc0 = sb[d0], bc1 = sb[d0 + 1];

    for (int t = fslot; t < NTILE; t += nslot) {
        int n0 = t * 128 + warp * 8;
        if (n0 >= Nn) continue;
        {
            int n = n0 + nt;
            bool v = n < Nn;
            const float4* xr = (const float4*)(x + (v ? n : 0) * Ff) + cg * 8;
#pragma unroll
            for (int q = 0; q < 8; q++) {
                float4 tv = v ? xr[q] : make_float4(0, 0, 0, 0);
                int c = cg * 32 + q * 4;
                sXw[(c + 0) * 10 + nt] = tv.x;
                sXw[(c + 1) * 10 + nt] = tv.y;
                sXw[(c + 2) * 10 + nt] = tv.z;
                sXw[(c + 3) * 10 + nt] = tv.w;
            }
        }
        __syncwarp();
        u64 acc[4][2];
#pragma unroll
        for (int p = 0; p < 4; p++) { acc[p][0] = 0ull; acc[p][1] = 0ull; }
#pragma unroll 4
        for (int k = 0; k < Ff; k++) {
            float2 w = *(const float2*)(sW + k * 64 + d0);
            u64 sw0 = splat2(w.x), sw1 = splat2(w.y);
            const u64* xp = (const u64*)(sXw + k * 10);
#pragma unroll
            for (int p = 0; p < 4; p++) {
                u64 xv = xp[p];
                acc[p][0] = ffma2(xv, sw0, acc[p][0]);
                acc[p][1] = ffma2(xv, sw1, acc[p][1]);
            }
        }
#pragma unroll
        for (int p = 0; p < 4; p++) {
            float2 a0 = unpk(acc[p][0]), a1 = unpk(acc[p][1]);
            int na = n0 + 2 * p, nb = na + 1;
            if (na < Nn) *(float2*)(out + na * 64 + d0) = make_float2(a0.x + bc0, a1.x + bc1);
            if (nb < Nn) *(float2*)(out + nb * 64 + d0) = make_float2(a0.y + bc0, a1.y + bc1);
        }
        __syncwarp();
    }
}

// ---------------- fused layer: mma.sync bf16, A-reuse + j-pair B loads ----------------
#define SM_AGH 0
#define SM_AGL 18432
#define SM_HH  36864
#define SM_HL  55296
#define SM_CONV 73728        // relH 8K, relL 8K, rootH 8K, rootL 8K
#define SM_GRU  106496       // ihH 16K, ihL 16K, hhH 16K, hhL 16K, inH 8K, inL 8K, hnH 8K, hnL 8K
#define SM_BREL 204800
#define SM_BIH  205056
#define SM_BHH  205824
#define LAYER_SHM 206592

// 4 MMAs (conv/n-gate layout: pair index = ks*4 + nh*2 + jp)
#define MM4(ACC, A, BOFF) do { \
    const uint4* _b = (const uint4*)(sm + (BOFF)); \
    _Pragma("unroll") \
    for (int jp = 0; jp < 2; jp++) { \
        uint4 q = _b[(ks * 4 + nh * 2 + jp) * 32 + lane]; \
        mmaf(ACC[2 * jp],     A, make_uint2(q.x, q.y)); \
        mmaf(ACC[2 * jp + 1], A, make_uint2(q.z, q.w)); \
    } \
} while (0)

// 8 MMAs (rz layout: pair index = ks*8 + {nh*2, 4+nh*2} + jp)
#define MMRZ(A, BOFF) do { \
    const uint4* _b = (const uint4*)(sm + (BOFF)); \
    _Pragma("unroll") \
    for (int jp = 0; jp < 2; jp++) { \
        uint4 q = _b[(ks * 8 + nh * 2 + jp) * 32 + lane]; \
        mmaf(accRZ[2 * jp],     A, make_uint2(q.x, q.y)); \
        mmaf(accRZ[2 * jp + 1], A, make_uint2(q.z, q.w)); \
        uint4 q2 = _b[(ks * 8 + 4 + nh * 2 + jp) * 32 + lane]; \
        mmaf(accRZ[4 + 2 * jp],     A, make_uint2(q2.x, q2.y)); \
        mmaf(accRZ[4 + 2 * jp + 1], A, make_uint2(q2.z, q2.w)); \
    } \
} while (0)

__global__ __launch_bounds__(512, 1) void k_layer(const float* __restrict__ in_base,
                                                  float* __restrict__ out_base,
                                                  int layer,
                                                  const float* __restrict__ brel_all,
                                                  const float* __restrict__ bih_all,
                                                  const float* __restrict__ bhh_all) {
    extern __shared__ unsigned char sm[];
    u32 smb = smem_u32(sm);
    int tid = threadIdx.x, warp = tid >> 5, lane = tid & 31;
    int f = blockIdx.x & 3;
    int fslot = blockIdx.x >> 2;
    int nslot = gridDim.x >> 2;
    int wl = f * NLl + layer;
    const float* in_state = in_base + f * Nn * Dd;
    float* out_state = out_base + f * Nn * Dd;
    const float* wfp = g_wcsr + f * Ee;

    {   // weights + biases -> smem
        const uint4* pc = (const uint4*)(g_pkconv + wl * 4096);
        uint4* dc = (uint4*)(sm + SM_CONV);
        for (int i = tid; i < 2048; i += 512) dc[i] = pc[i];
        const uint4* pg = (const uint4*)(g_pkgru + f * 12288);
        uint4* dg = (uint4*)(sm + SM_GRU);
        for (int i = tid; i < 6144; i += 512) dg[i] = pg[i];
        float* sb = (float*)(sm + SM_BREL);
        if (tid < 64) sb[tid] = brel_all[wl * 64 + tid];
        float* si = (float*)(sm + SM_BIH);
        float* shh = (float*)(sm + SM_BHH);
        if (tid < 192) { si[tid] = bih_all[f * 192 + tid]; shh[tid] = bhh_all[f * 192 + tid]; }
    }
    __syncthreads();

    int mt = warp >> 1, nh = warp & 1;
    int g = lane >> 2, s = lane & 3;
    u32 aoff = (u32)((mt * 16 + (lane & 15)) * 144 + (lane >> 4) * 16);
    int nl = tid >> 2, cg = tid & 3;
    const float* sbrel = (const float*)(sm + SM_BREL);
    const float* sbih  = (const float*)(sm + SM_BIH);
    const float* sbhh  = (const float*)(sm + SM_BHH);

    for (int t = fslot; t < NTILE; t += nslot) {
        int n0 = t * 128;

        // ---- stage: agg (fp32, edge prefetch) + h -> bf16 hi/lo tiles ----
        {
            int gn = n0 + nl;
            bool v = gn < Nn;
            float hv[16], acc[16];
            const float4* hr = (const float4*)(in_state + (v ? gn : 0) * 64 + cg * 16);
#pragma unroll
            for (int q = 0; q < 4; q++) {
                float4 tv = v ? hr[q] : make_float4(0, 0, 0, 0);
                hv[4 * q] = tv.x; hv[4 * q + 1] = tv.y; hv[4 * q + 2] = tv.z; hv[4 * q + 3] = tv.w;
            }
#pragma unroll
            for (int ii = 0; ii < 16; ii++) acc[ii] = 0.f;
            if (v) {
                int beg = g_rowptr[gn], end = g_rowptr[gn + 1];
                int sn_pf = 0; float w_pf = 0.f;
                if (beg < end) { sn_pf = g_srcs[beg]; w_pf = wfp[beg]; }
                for (int j = beg; j < end; j++) {
                    int sn = sn_pf; float w = w_pf;
                    if (j + 1 < end) { sn_pf = g_srcs[j + 1]; w_pf = wfp[j + 1]; }
                    const float4* sr = (const float4*)(in_state + sn * 64 + cg * 16);
#pragma unroll
                    for (int q = 0; q < 4; q++) {
                        float4 tv = sr[q];
                        acc[4 * q] += w * tv.x; acc[4 * q + 1] += w * tv.y;
                        acc[4 * q + 2] += w * tv.z; acc[4 * q + 3] += w * tv.w;
                    }
                }
            }
#pragma unroll
            for (int ii = 0; ii < 8; ii++) {
                int c = cg * 16 + 2 * ii;
                u32 off = (u32)(nl * 144 + c * 2);
                u32 hi, lo;
                split2(acc[2 * ii], acc[2 * ii + 1], hi, lo);
                *(u32*)(sm + SM_AGH + off) = hi;
                *(u32*)(sm + SM_AGL + off) = lo;
                split2(hv[2 * ii], hv[2 * ii + 1], hi, lo);
                *(u32*)(sm + SM_HH + off) = hi;
                *(u32*)(sm + SM_HL + off) = lo;
            }
        }
        __syncthreads();

        // ---- conv GEMM (A-major: 4 ldmatrix per kstep) ----
        float accC[4][4];
#pragma unroll
        for (int a = 0; a < 4; a++)
#pragma unroll
            for (int b = 0; b < 4; b++) accC[a][b] = 0.f;
#pragma unroll
        for (int ks = 0; ks < 4; ks++) {
            uint4 a = ldm(smb + SM_AGH + aoff + ks * 32);
            MM4(accC, a, SM_CONV);
            MM4(accC, a, SM_CONV + 8192);
            a = ldm(smb + SM_AGL + aoff + ks * 32);
            MM4(accC, a, SM_CONV);
            a = ldm(smb + SM_HH + aoff + ks * 32);
            MM4(accC, a, SM_CONV + 16384);
            MM4(accC, a, SM_CONV + 24576);
            a = ldm(smb + SM_HL + aoff + ks * 32);
            MM4(accC, a, SM_CONV + 16384);
        }
        __syncthreads();

        // ---- epilogue 1: m = relu(conv + brel) -> overwrite agg tiles ----
        {
#pragma unroll
            for (int j = 0; j < 4; j++) {
                int c = nh * 32 + j * 8 + 2 * s;
                u32 off = (u32)((mt * 16 + g) * 144 + c * 2);
                u32 hi, lo;
                float m0 = fmaxf(accC[j][0] + sbrel[c], 0.f);
                float m1 = fmaxf(accC[j][1] + sbrel[c + 1], 0.f);
                split2(m0, m1, hi, lo);
                *(u32*)(sm + SM_AGH + off) = hi;
                *(u32*)(sm + SM_AGL + off) = lo;
                m0 = fmaxf(accC[j][2] + sbrel[c], 0.f);
                m1 = fmaxf(accC[j][3] + sbrel[c + 1], 0.f);
                split2(m0, m1, hi, lo);
                *(u32*)(sm + SM_AGH + off + 8 * 144) = hi;
                *(u32*)(sm + SM_AGL + off + 8 * 144) = lo;
            }
        }
        __syncthreads();

        // ---- merged GRU GEMMs (rz + inn + hn, A-major: 4 ldmatrix per kstep) ----
        float accRZ[8][4], accI[4][4], accH[4][4];
#pragma unroll
        for (int a = 0; a < 8; a++)
#pragma unroll
            for (int b = 0; b < 4; b++) accRZ[a][b] = 0.f;
#pragma unroll
        for (int a = 0; a < 4; a++)
#pragma unroll
            for (int b = 0; b < 4; b++) { accI[a][b] = 0.f; accH[a][b] = 0.f; }
#pragma unroll
        for (int ks = 0; ks < 4; ks++) {
            uint4 a = ldm(smb + SM_AGH + aoff + ks * 32);
            MMRZ(a, SM_GRU);                // m(hi) @ ih(hi)
            MMRZ(a, SM_GRU + 16384);        // m(hi) @ ih(lo)
            MM4(accI, a, SM_GRU + 65536);   // m(hi) @ in(hi)
            MM4(accI, a, SM_GRU + 73728);   // m(hi) @ in(lo)
            a = ldm(smb + SM_AGL + aoff + ks * 32);
            MMRZ(a, SM_GRU);                // m(lo) @ ih(hi)
            MM4(accI, a, SM_GRU + 65536);   // m(lo) @ in(hi)
            a = ldm(smb + SM_HH + aoff + ks * 32);
            MMRZ(a, SM_GRU + 32768);        // h(hi) @ hh(hi)
            MMRZ(a, SM_GRU + 49152);        // h(hi) @ hh(lo)
            MM4(accH, a, SM_GRU + 81920);   // h(hi) @ hn(hi)
            MM4(accH, a, SM_GRU + 90112);   // h(hi) @ hn(lo)
            a = ldm(smb + SM_HL + aoff + ks * 32);
            MMRZ(a, SM_GRU + 32768);        // h(lo) @ hh(hi)
            MM4(accH, a, SM_GRU + 81920);   // h(lo) @ hn(hi)
        }

        // ---- epilogue 2: gates + blend + store (register-resident) ----
        {
#pragma unroll
            for (int j = 0; j < 4; j++) {
                int c = nh * 32 + j * 8 + 2 * s;
#pragma unroll
                for (int q = 0; q < 2; q++) {
                    int row = mt * 16 + g + q * 8;
                    int gn = n0 + row;
                    if (gn < Nn) {
                        float r0v = sigm(accRZ[j][2 * q]     + sbih[c]     + sbhh[c]);
                        float r1v = sigm(accRZ[j][2 * q + 1] + sbih[c + 1] + sbhh[c + 1]);
                        float z0v = sigm(accRZ[4 + j][2 * q]     + sbih[64 + c]     + sbhh[64 + c]);
                        float z1v = sigm(accRZ[4 + j][2 * q + 1] + sbih[64 + c + 1] + sbhh[64 + c + 1]);
                        float nn0 = tanh_f(accI[j][2 * q]     + sbih[128 + c]     + r0v * (accH[j][2 * q]     + sbhh[128 + c]));
                        float nn1 = tanh_f(accI[j][2 * q + 1] + sbih[128 + c + 1] + r1v * (accH[j][2 * q + 1] + sbhh[128 + c + 1]));
                        float2 hp = *(const float2*)(in_state + gn * 64 + c);
                        float o0 = (1.f - z0v) * nn0 + z0v * hp.x;
                        float o1 = (1.f - z1v) * nn1 + z1v * hp.y;
                        *(float2*)(out_state + gn * 64 + c) = make_float2(o0, o1);
                    }
                }
            }
        }
        __syncthreads();
    }
}

// ---------------- global mean pool ----------------
__global__ void k_pool(const float* __restrict__ feats, float* __restrict__ out) {
    int g = blockIdx.x, f = blockIdx.y, d = threadIdx.x;  // blockDim = 64
    int s = g_gstart[g], e = g_gstart[g + 1];
    const float* base = feats + f * Nn * Dd;
    float s0 = 0.f, s1 = 0.f, s2 = 0.f, s3 = 0.f;
    int i = s;
    for (; i + 3 < e; i += 4) {
        s0 += base[i * Dd + d];
        s1 += base[(i + 1) * Dd + d];
        s2 += base[(i + 2) * Dd + d];
        s3 += base[(i + 3) * Dd + d];
    }
    for (; i < e; i++) s0 += base[i * Dd + d];
    float sum = (s0 + s1) + (s2 + s3);
    int cnt = e - s;
    if (cnt < 1) cnt = 1;
    out[(f * Gg + g) * Dd + d] = sum / (float)cnt;
}

// ---------------- host ----------------
extern "C" void kernel_launch(void* const* d_in, const int* in_sizes, int n_in,
                              void* d_out, int out_size) {
    const float* x     = (const float*)d_in[0];
    const int*   ei    = (const int*)d_in[1];
    const float* att   = (const float*)d_in[2];
    const int*   batch = (const int*)d_in[3];
    const float* lin_W = (const float*)d_in[4];
    const float* lin_b = (const float*)d_in[5];
    const float* Wrel  = (const float*)d_in[6];
    const float* brel  = (const float*)d_in[7];
    const float* Wroot = (const float*)d_in[8];
    const float* Wih   = (const float*)d_in[9];
    const float* Whh   = (const float*)d_in[10];
    const float* bih   = (const float*)d_in[11];
    const float* bhh   = (const float*)d_in[12];

    float* out = (float*)d_out;
    float* feats = out + NFf * Gg * Dd;
    const int* srcp = ei;
    const int* dstp = ei + Ee;

    int sm = 148;
    cudaDeviceGetAttribute(&sm, cudaDevAttrMultiProcessorCount, 0);
    int grid = (sm / 4) * 4;
    if (grid < 4) grid = 4;

    cudaFuncSetAttribute(k_layer, cudaFuncAttributeMaxDynamicSharedMemorySize, LAYER_SHM);
    cudaFuncSetAttribute(k_lin, cudaFuncAttributeMaxDynamicSharedMemorySize, LIN_SHM);

    void *pa, *pb;
    cudaGetSymbolAddress(&pa, g_stateA);
    cudaGetSymbolAddress(&pb, g_stateB);
    float* A = (float*)pa;
    float* B = (float*)pb;

    const int NB = (Nn + 1023) / 1024;

    k_zero<<<(Nn + 255) / 256, 256>>>();
    k_hist<<<(Ee + 255) / 256, 256>>>(dstp, batch);
    k_scan1<<<NB, 1024>>>();
    k_scan2<<<1, 32>>>(NB);
    k_scan3<<<NB, 1024>>>();
    k_scatter<<<(Ee + 255) / 256, 256>>>(srcp, dstp);
    k_sortseg<<<(Nn + 127) / 128, 128>>>();
    k_buildw<<<(Ee + 255) / 256, 256>>>(att);
    k_gscan<<<1, 32>>>();
    k_pack<<<(98304 + 255) / 256, 256>>>(Wrel, Wroot, Wih, Whh);

    k_lin<<<grid, 512, LIN_SHM>>>(x, lin_W, lin_b, A);
    k_layer<<<grid, 512, LAYER_SHM>>>(A, B, 0, brel, bih, bhh);
    k_layer<<<grid, 512, LAYER_SHM>>>(B, A, 1, brel, bih, bhh);
    k_layer<<<grid, 512, LAYER_SHM>>>(A, feats, 2, brel, bih, bhh);
    k_pool<<<dim3(Gg, NFf), 64>>>(feats, out);
}

// round 14
// speedup vs baseline: 1.0924x; 1.0924x over previous
#include <cuda_runtime.h>
#include <cuda_bf16.h>
#include <math.h>

typedef unsigned long long u64;
typedef unsigned int u32;

#define Nn 100000
#define Ee 1600000
#define Ff 128
#define NFf 4
#define Dd 64
#define NLl 3
#define Gg 128
#define NTILE 782   // ceil(Nn/128)

// ---------------- device scratch (no allocations allowed) ----------------
__device__ int   g_deg[Nn];
__device__ int   g_rowptr[Nn + 1];
__device__ int   g_fill[Nn];
__device__ int   g_bsums[256];
__device__ int   g_srcs[Ee];
__device__ int   g_eids[Ee];
__device__ float g_wcsr[NFf * Ee];
__device__ float g_stateA[NFf * Nn * Dd];
__device__ float g_stateB[NFf * Nn * Dd];
__device__ int   g_gcnt[Gg];
__device__ int   g_gstart[Gg + 1];
// fragment-packed bf16 weights (uint2 per lane-fragment) — R11 layout
__device__ uint2 g_pkconv[12 * 4096];   // [wl][mat:relH,relL,rootH,rootL][ks4][nt8][lane32]
__device__ uint2 g_pkgru[4 * 12288];    // [f][ihH2048,ihL2048,hhH2048,hhL2048,inH1024,inL1024,hnH1024,hnL1024]

// ---------------- helpers ----------------
__device__ __forceinline__ u64 ffma2(u64 a, u64 b, u64 c) {
    u64 d; asm("fma.rn.f32x2 %0,%1,%2,%3;" : "=l"(d) : "l"(a), "l"(b), "l"(c)); return d;
}
__device__ __forceinline__ u64 splat2(float v) {
    u64 d; u32 r = __float_as_uint(v);
    asm("mov.b64 %0,{%1,%2};" : "=l"(d) : "r"(r), "r"(r)); return d;
}
__device__ __forceinline__ float2 unpk(u64 v) {
    u32 lo, hi; asm("mov.b64 {%0,%1},%2;" : "=r"(lo), "=r"(hi) : "l"(v));
    return make_float2(__uint_as_float(lo), __uint_as_float(hi));
}
__device__ __forceinline__ float sigm(float v) { return 1.f / (1.f + __expf(-v)); }
__device__ __forceinline__ float tanh_f(float v) { return 2.f / (1.f + __expf(-2.f * v)) - 1.f; }

__device__ __forceinline__ u32 smem_u32(const void* p) {
    u32 a;
    asm("{ .reg .u64 t; cvta.to.shared.u64 t, %1; cvt.u32.u64 %0, t; }" : "=r"(a) : "l"(p));
    return a;
}

__device__ __forceinline__ void split2(float a0, float a1, u32& hi, u32& lo) {
    __nv_bfloat16 h0 = __float2bfloat16(a0), h1 = __float2bfloat16(a1);
    __nv_bfloat162 hp = __halves2bfloat162(h0, h1);
    float r0 = a0 - __bfloat162float(h0);
    float r1 = a1 - __bfloat162float(h1);
    __nv_bfloat162 lp = __floats2bfloat162_rn(r0, r1);
    hi = *(u32*)&hp; lo = *(u32*)&lp;
}

__device__ __forceinline__ u32 pkbf(float a, float b, bool lo) {
    __nv_bfloat16 ah = __float2bfloat16(a), bh = __float2bfloat16(b);
    if (lo) {
        ah = __float2bfloat16(a - __bfloat162float(ah));
        bh = __float2bfloat16(b - __bfloat162float(bh));
    }
    __nv_bfloat162 p = __halves2bfloat162(ah, bh);
    return *(u32*)&p;
}

__device__ __forceinline__ uint4 ldm(u32 addr) {
    uint4 r;
    asm volatile("ldmatrix.sync.aligned.m8n8.x4.shared.b16 {%0,%1,%2,%3}, [%4];"
        : "=r"(r.x), "=r"(r.y), "=r"(r.z), "=r"(r.w) : "r"(addr));
    return r;
}
__device__ __forceinline__ void mmaf(float d[4], uint4 a, uint2 b) {
    asm volatile("mma.sync.aligned.m16n8k16.row.col.f32.bf16.bf16.f32 "
        "{%0,%1,%2,%3}, {%4,%5,%6,%7}, {%8,%9}, {%0,%1,%2,%3};"
        : "+f"(d[0]), "+f"(d[1]), "+f"(d[2]), "+f"(d[3])
        : "r"(a.x), "r"(a.y), "r"(a.z), "r"(a.w), "r"(b.x), "r"(b.y));
}

// ---------------- CSR build ----------------
__global__ void k_zero() {
    int i = blockIdx.x * blockDim.x + threadIdx.x;
    if (i < Nn) g_deg[i] = 0;
    if (i < Gg) g_gcnt[i] = 0;
}

__global__ void k_hist(const int* __restrict__ dst, const int* __restrict__ batch) {
    int i = blockIdx.x * blockDim.x + threadIdx.x;
    if (i < Ee) atomicAdd(&g_deg[dst[i]], 1);
    if (i < Nn) atomicAdd(&g_gcnt[batch[i]], 1);
}

__global__ void k_scan1() {
    __shared__ int tmp[1024];
    int i = blockIdx.x * 1024 + threadIdx.x;
    int v = (i < Nn) ? g_deg[i] : 0;
    tmp[threadIdx.x] = v;
    __syncthreads();
    for (int off = 1; off < 1024; off <<= 1) {
        int t = 0;
        if (threadIdx.x >= off) t = tmp[threadIdx.x - off];
        __syncthreads();
        if (threadIdx.x >= off) tmp[threadIdx.x] += t;
        __syncthreads();
    }
    if (i < Nn) g_rowptr[i + 1] = tmp[threadIdx.x];
    if (threadIdx.x == 1023) g_bsums[blockIdx.x] = tmp[1023];
}

__global__ void k_scan2(int nb) {
    if (threadIdx.x == 0 && blockIdx.x == 0) {
        int run = 0;
        for (int b = 0; b < nb; b++) { int v = g_bsums[b]; g_bsums[b] = run; run += v; }
    }
}

__global__ void k_scan3() {
    int i = blockIdx.x * 1024 + threadIdx.x;
    if (i < Nn) {
        int v = g_rowptr[i + 1] + g_bsums[blockIdx.x];
        g_rowptr[i + 1] = v;
        if (i + 1 < Nn) g_fill[i + 1] = v;
    }
    if (i == 0) { g_rowptr[0] = 0; g_fill[0] = 0; }
}

__global__ void k_scatter(const int* __restrict__ src, const int* __restrict__ dst) {
    int e = blockIdx.x * blockDim.x + threadIdx.x;
    if (e < Ee) {
        int d = dst[e];
        int p = atomicAdd(&g_fill[d], 1);
        g_srcs[p] = src[e];
        g_eids[p] = e;
    }
}

__global__ void k_sortseg() {
    int n = blockIdx.x * blockDim.x + threadIdx.x;
    if (n >= Nn) return;
    int b = g_rowptr[n], e = g_rowptr[n + 1];
    for (int i = b + 1; i < e; i++) {
        int ke = g_eids[i], ks = g_srcs[i];
        int j = i - 1;
        while (j >= b && g_eids[j] > ke) {
            g_eids[j + 1] = g_eids[j];
            g_srcs[j + 1] = g_srcs[j];
            j--;
        }
        g_eids[j + 1] = ke;
        g_srcs[j + 1] = ks;
    }
}

__global__ void k_buildw(const float* __restrict__ att) {
    int j = blockIdx.x * blockDim.x + threadIdx.x;
    if (j < Ee) {
        int e = g_eids[j];
#pragma unroll
        for (int f = 0; f < NFf; f++) g_wcsr[f * Ee + j] = att[f * Ee + e];
    }
}

__global__ void k_gscan() {
    if (threadIdx.x == 0 && blockIdx.x == 0) {
        int run = 0;
        for (int g = 0; g < Gg; g++) { g_gstart[g] = run; run += g_gcnt[g]; }
        g_gstart[Gg] = run;
    }
}

// ---------------- weight pre-pack (R11 layout, unchanged) ----------------
__global__ void k_pack(const float* __restrict__ Wrel, const float* __restrict__ Wroot,
                       const float* __restrict__ Wih, const float* __restrict__ Whh) {
    int i = blockIdx.x * blockDim.x + threadIdx.x;
    if (i >= 98304) return;
    float v00, v01, v10, v11;
    bool lo;
    uint2* dst;
    if (i < 49152) {
        int wl = i >> 12;
        int r = i & 4095;
        int mat = r >> 10;          // 0 relH, 1 relL, 2 rootH, 3 rootL
        int fr = r & 1023;
        int ks = fr >> 8, nt = (fr >> 5) & 7, lane = fr & 31;
        int s = lane & 3, n = nt * 8 + (lane >> 2);
        int k0 = ks * 16 + 2 * s;
        const float* Wm = ((mat >= 2) ? Wroot : Wrel) + wl * 4096;  // B[k][n] = W[k*64+n]
        v00 = Wm[k0 * 64 + n];       v01 = Wm[(k0 + 1) * 64 + n];
        v10 = Wm[(k0 + 8) * 64 + n]; v11 = Wm[(k0 + 9) * 64 + n];
        lo = (mat & 1);
        dst = g_pkconv + i;
    } else {
        int j = i - 49152;
        int f = j / 12288;
        int r = j % 12288;
        const float* WI = Wih + f * 12288;
        const float* WH = Whh + f * 12288;
        if (r < 8192) {             // rz: ihH, ihL, hhH, hhL
            int mat = r >> 11;
            int fr = r & 2047;
            int ks = fr >> 9, nt = (fr >> 5) & 15, lane = fr & 31;
            int s = lane & 3, n = nt * 8 + (lane >> 2);
            int k0 = ks * 16 + 2 * s;
            const float* Wm = (mat >= 2) ? WH : WI;        // B[k][n] = W[n*64+k]
            v00 = Wm[n * 64 + k0];     v01 = Wm[n * 64 + k0 + 1];
            v10 = Wm[n * 64 + k0 + 8]; v11 = Wm[n * 64 + k0 + 9];
            lo = (mat & 1);
        } else {                    // n gate: inH, inL, hnH, hnL
            int rn = r - 8192;
            int mat = rn >> 10;
            int fr = rn & 1023;
            int ks = fr >> 8, nt = (fr >> 5) & 7, lane = fr & 31;
            int s = lane & 3, n = nt * 8 + (lane >> 2);
            int k0 = ks * 16 + 2 * s;
            const float* Wm = (mat >= 2) ? WH : WI;        // B[k][n] = W[(128+n)*64+k]
            v00 = Wm[(128 + n) * 64 + k0];     v01 = Wm[(128 + n) * 64 + k0 + 1];
            v10 = Wm[(128 + n) * 64 + k0 + 8]; v11 = Wm[(128 + n) * 64 + k0 + 9];
            lo = (mat & 1);
        }
        dst = g_pkgru + j;
    }
    *dst = make_uint2(pkbf(v00, v01, lo), pkbf(v10, v11, lo));
}

// ---------------- lin (FFMA champion, unchanged) ----------------
#define LIN_SHM ((8192 + 64 + 16 * 1280) * 4)
__global__ __launch_bounds__(512, 1) void k_lin(const float* __restrict__ x,
                                                const float* __restrict__ W_all,
                                                const float* __restrict__ b_all,
                                                float* __restrict__ out_base) {
    extern __shared__ float sh[];
    float* sW = sh;
    float* sb = sW + 8192;
    float* sX = sb + 64;
    int f = blockIdx.x & 3;
    int fslot = blockIdx.x >> 2;
    int nslot = gridDim.x >> 2;
    const float* W = W_all + f * Ff * Dd;
    const float* b = b_all + f * Dd;
    float* out = out_base + f * Nn * Dd;

    int tid = threadIdx.x;
    for (int i = tid; i < 8192; i += 512) sW[i] = W[i];
    if (tid < 64) sb[tid] = b[tid];
    __syncthreads();
    int warp = tid >> 5, lane = tid & 31;
    int d0 = 2 * lane;
    int nt = lane >> 2, cg = lane & 3;
    float* sXw = sX + warp * 1280;
    float bc0 = sb[d0], bc1 = sb[d0 + 1];

    for (int t = fslot; t < NTILE; t += nslot) {
        int n0 = t * 128 + warp * 8;
        if (n0 >= Nn) continue;
        {
            int n = n0 + nt;
            bool v = n < Nn;
            const float4* xr = (const float4*)(x + (v ? n : 0) * Ff) + cg * 8;
#pragma unroll
            for (int q = 0; q < 8; q++) {
                float4 tv = v ? xr[q] : make_float4(0, 0, 0, 0);
                int c = cg * 32 + q * 4;
                sXw[(c + 0) * 10 + nt] = tv.x;
                sXw[(c + 1) * 10 + nt] = tv.y;
                sXw[(c + 2) * 10 + nt] = tv.z;
                sXw[(c + 3) * 10 + nt] = tv.w;
            }
        }
        __syncwarp();
        u64 acc[4][2];
#pragma unroll
        for (int p = 0; p < 4; p++) { acc[p][0] = 0ull; acc[p][1] = 0ull; }
#pragma unroll 4
        for (int k = 0; k < Ff; k++) {
            float2 w = *(const float2*)(sW + k * 64 + d0);
            u64 sw0 = splat2(w.x), sw1 = splat2(w.y);
            const u64* xp = (const u64*)(sXw + k * 10);
#pragma unroll
            for (int p = 0; p < 4; p++) {
                u64 xv = xp[p];
                acc[p][0] = ffma2(xv, sw0, acc[p][0]);
                acc[p][1] = ffma2(xv, sw1, acc[p][1]);
            }
        }
#pragma unroll
        for (int p = 0; p < 4; p++) {
            float2 a0 = unpk(acc[p][0]), a1 = unpk(acc[p][1]);
            int na = n0 + 2 * p, nb = na + 1;
            if (na < Nn) *(float2*)(out + na * 64 + d0) = make_float2(a0.x + bc0, a1.x + bc1);
            if (nb < Nn) *(float2*)(out + nb * 64 + d0) = make_float2(a0.y + bc0, a1.y + bc1);
        }
        __syncwarp();
    }
}

// ---------------- fused layer: mma.sync bf16 (R11 base, A-frag reuse) ----------------
#define SM_AGH 0
#define SM_AGL 18432
#define SM_HH  36864
#define SM_HL  55296
#define SM_CONV 73728        // relH 8K, relL 8K, rootH 8K, rootL 8K
#define SM_GRU  106496       // ihH 16K, ihL 16K, hhH 16K, hhL 16K, inH 8K, inL 8K, hnH 8K, hnL 8K
#define SM_BREL 204800
#define SM_BIH  205056
#define SM_BHH  205824
#define LAYER_SHM 206592

// 4 MMAs against an 8-nt-block B matrix (conv / n-gate layout)
#define MM4(ACC, A, BOFF) do { \
    const uint2* _b = (const uint2*)(sm + (BOFF)); \
    _Pragma("unroll") \
    for (int j = 0; j < 4; j++) \
        mmaf(ACC[j], A, _b[(ks * 8 + nh * 4 + j) * 32 + lane]); \
} while (0)

// 8 MMAs against the 16-nt-block rz B matrix
#define MMRZ(A, BOFF) do { \
    const uint2* _b = (const uint2*)(sm + (BOFF)); \
    _Pragma("unroll") \
    for (int j = 0; j < 4; j++) \
        mmaf(accRZ[j], A, _b[(ks * 16 + nh * 4 + j) * 32 + lane]); \
    _Pragma("unroll") \
    for (int j = 0; j < 4; j++) \
        mmaf(accRZ[4 + j], A, _b[(ks * 16 + 8 + nh * 4 + j) * 32 + lane]); \
} while (0)

__global__ __launch_bounds__(512, 1) void k_layer(const float* __restrict__ in_base,
                                                  float* __restrict__ out_base,
                                                  int layer,
                                                  const float* __restrict__ brel_all,
                                                  const float* __restrict__ bih_all,
                                                  const float* __restrict__ bhh_all) {
    extern __shared__ unsigned char sm[];
    u32 smb = smem_u32(sm);
    int tid = threadIdx.x, warp = tid >> 5, lane = tid & 31;
    int f = blockIdx.x & 3;
    int fslot = blockIdx.x >> 2;
    int nslot = gridDim.x >> 2;
    int wl = f * NLl + layer;
    const float* in_state = in_base + f * Nn * Dd;
    float* out_state = out_base + f * Nn * Dd;
    const float* wfp = g_wcsr + f * Ee;

    {   // weights + biases -> smem
        const uint4* pc = (const uint4*)(g_pkconv + wl * 4096);
        uint4* dc = (uint4*)(sm + SM_CONV);
        for (int i = tid; i < 2048; i += 512) dc[i] = pc[i];
        const uint4* pg = (const uint4*)(g_pkgru + f * 12288);
        uint4* dg = (uint4*)(sm + SM_GRU);
        for (int i = tid; i < 6144; i += 512) dg[i] = pg[i];
        float* sb = (float*)(sm + SM_BREL);
        if (tid < 64) sb[tid] = brel_all[wl * 64 + tid];
        float* si = (float*)(sm + SM_BIH);
        float* shh = (float*)(sm + SM_BHH);
        if (tid < 192) { si[tid] = bih_all[f * 192 + tid]; shh[tid] = bhh_all[f * 192 + tid]; }
    }
    __syncthreads();

    int mt = warp >> 1, nh = warp & 1;
    int g = lane >> 2, s = lane & 3;
    u32 aoff = (u32)((mt * 16 + (lane & 15)) * 144 + (lane >> 4) * 16);
    int nl = tid >> 2, cg = tid & 3;
    const float* sbrel = (const float*)(sm + SM_BREL);
    const float* sbih  = (const float*)(sm + SM_BIH);
    const float* sbhh  = (const float*)(sm + SM_BHH);

    for (int t = fslot; t < NTILE; t += nslot) {
        int n0 = t * 128;

        // ---- stage: agg (fp32) + h -> bf16 hi/lo tiles ----
        {
            int gn = n0 + nl;
            bool v = gn < Nn;
            float hv[16], acc[16];
            const float4* hr = (const float4*)(in_state + (v ? gn : 0) * 64 + cg * 16);
#pragma unroll
            for (int q = 0; q < 4; q++) {
                float4 tv = v ? hr[q] : make_float4(0, 0, 0, 0);
                hv[4 * q] = tv.x; hv[4 * q + 1] = tv.y; hv[4 * q + 2] = tv.z; hv[4 * q + 3] = tv.w;
            }
#pragma unroll
            for (int ii = 0; ii < 16; ii++) acc[ii] = 0.f;
            if (v) {
                int beg = g_rowptr[gn], end = g_rowptr[gn + 1];
                for (int j = beg; j < end; j++) {
                    int sn = g_srcs[j];
                    float w = wfp[j];
                    const float4* sr = (const float4*)(in_state + sn * 64 + cg * 16);
#pragma unroll
                    for (int q = 0; q < 4; q++) {
                        float4 tv = sr[q];
                        acc[4 * q] += w * tv.x; acc[4 * q + 1] += w * tv.y;
                        acc[4 * q + 2] += w * tv.z; acc[4 * q + 3] += w * tv.w;
                    }
                }
            }
#pragma unroll
            for (int ii = 0; ii < 8; ii++) {
                int c = cg * 16 + 2 * ii;
                u32 off = (u32)(nl * 144 + c * 2);
                u32 hi, lo;
                split2(acc[2 * ii], acc[2 * ii + 1], hi, lo);
                *(u32*)(sm + SM_AGH + off) = hi;
                *(u32*)(sm + SM_AGL + off) = lo;
                split2(hv[2 * ii], hv[2 * ii + 1], hi, lo);
                *(u32*)(sm + SM_HH + off) = hi;
                *(u32*)(sm + SM_HL + off) = lo;
            }
        }
        __syncthreads();

        // ---- Loop A: conv GEMM + hn GEMM (A-major; HH/HL frags shared) ----
        float accC[4][4], accH[4][4];
#pragma unroll
        for (int a = 0; a < 4; a++)
#pragma unroll
            for (int b = 0; b < 4; b++) { accC[a][b] = 0.f; accH[a][b] = 0.f; }
#pragma unroll
        for (int ks = 0; ks < 4; ks++) {
            uint4 a = ldm(smb + SM_AGH + aoff + ks * 32);
            MM4(accC, a, SM_CONV);              // agg(hi) @ rel(hi)
            MM4(accC, a, SM_CONV + 8192);       // agg(hi) @ rel(lo)
            a = ldm(smb + SM_AGL + aoff + ks * 32);
            MM4(accC, a, SM_CONV);              // agg(lo) @ rel(hi)
            a = ldm(smb + SM_HH + aoff + ks * 32);
            MM4(accC, a, SM_CONV + 16384);      // h(hi) @ root(hi)
            MM4(accC, a, SM_CONV + 24576);      // h(hi) @ root(lo)
            MM4(accH, a, SM_GRU + 81920);       // h(hi) @ hn(hi)
            MM4(accH, a, SM_GRU + 90112);       // h(hi) @ hn(lo)
            a = ldm(smb + SM_HL + aoff + ks * 32);
            MM4(accC, a, SM_CONV + 16384);      // h(lo) @ root(hi)
            MM4(accH, a, SM_GRU + 81920);       // h(lo) @ hn(hi)
        }
        __syncthreads();

        // ---- epilogue 1: m = relu(conv + brel) -> overwrite agg tiles ----
        {
#pragma unroll
            for (int j = 0; j < 4; j++) {
                int c = nh * 32 + j * 8 + 2 * s;
                u32 off = (u32)((mt * 16 + g) * 144 + c * 2);
                u32 hi, lo;
                float m0 = fmaxf(accC[j][0] + sbrel[c], 0.f);
                float m1 = fmaxf(accC[j][1] + sbrel[c + 1], 0.f);
                split2(m0, m1, hi, lo);
                *(u32*)(sm + SM_AGH + off) = hi;
                *(u32*)(sm + SM_AGL + off) = lo;
                m0 = fmaxf(accC[j][2] + sbrel[c], 0.f);
                m1 = fmaxf(accC[j][3] + sbrel[c + 1], 0.f);
                split2(m0, m1, hi, lo);
                *(u32*)(sm + SM_AGH + off + 8 * 144) = hi;
                *(u32*)(sm + SM_AGL + off + 8 * 144) = lo;
            }
        }
        __syncthreads();

        // ---- Loop B: rz GEMM + in GEMM (A-major) ----
        float accRZ[8][4], accI[4][4];
#pragma unroll
        for (int a = 0; a < 8; a++)
#pragma unroll
            for (int b = 0; b < 4; b++) accRZ[a][b] = 0.f;
#pragma unroll
        for (int a = 0; a < 4; a++)
#pragma unroll
            for (int b = 0; b < 4; b++) accI[a][b] = 0.f;
#pragma unroll
        for (int ks = 0; ks < 4; ks++) {
            uint4 a = ldm(smb + SM_AGH + aoff + ks * 32);
            MMRZ(a, SM_GRU);                    // m(hi) @ ih(hi)
            MMRZ(a, SM_GRU + 16384);            // m(hi) @ ih(lo)
            MM4(accI, a, SM_GRU + 65536);       // m(hi) @ in(hi)
            MM4(accI, a, SM_GRU + 73728);       // m(hi) @ in(lo)
            a = ldm(smb + SM_AGL + aoff + ks * 32);
            MMRZ(a, SM_GRU);                    // m(lo) @ ih(hi)
            MM4(accI, a, SM_GRU + 65536);       // m(lo) @ in(hi)
            a = ldm(smb + SM_HH + aoff + ks * 32);
            MMRZ(a, SM_GRU + 32768);            // h(hi) @ hh(hi)
            MMRZ(a, SM_GRU + 49152);            // h(hi) @ hh(lo)
            a = ldm(smb + SM_HL + aoff + ks * 32);
            MMRZ(a, SM_GRU + 32768);            // h(lo) @ hh(hi)
        }

        // ---- epilogue 2: gates + blend + store (register-resident) ----
        {
#pragma unroll
            for (int j = 0; j < 4; j++) {
                int c = nh * 32 + j * 8 + 2 * s;
#pragma unroll
                for (int q = 0; q < 2; q++) {
                    int row = mt * 16 + g + q * 8;
                    int gn = n0 + row;
                    if (gn < Nn) {
                        float r0v = sigm(accRZ[j][2 * q]     + sbih[c]     + sbhh[c]);
                        float r1v = sigm(accRZ[j][2 * q + 1] + sbih[c + 1] + sbhh[c + 1]);
                        float z0v = sigm(accRZ[4 + j][2 * q]     + sbih[64 + c]     + sbhh[64 + c]);
                        float z1v = sigm(accRZ[4 + j][2 * q + 1] + sbih[64 + c + 1] + sbhh[64 + c + 1]);
                        float nn0 = tanh_f(accI[j][2 * q]     + sbih[128 + c]     + r0v * (accH[j][2 * q]     + sbhh[128 + c]));
                        float nn1 = tanh_f(accI[j][2 * q + 1] + sbih[128 + c + 1] + r1v * (accH[j][2 * q + 1] + sbhh[128 + c + 1]));
                        float2 hp = *(const float2*)(in_state + gn * 64 + c);
                        float o0 = (1.f - z0v) * nn0 + z0v * hp.x;
                        float o1 = (1.f - z1v) * nn1 + z1v * hp.y;
                        *(float2*)(out_state + gn * 64 + c) = make_float2(o0, o1);
                    }
                }
            }
        }
        __syncthreads();
    }
}

// ---------------- global mean pool ----------------
__global__ void k_pool(const float* __restrict__ feats, float* __restrict__ out) {
    int g = blockIdx.x, f = blockIdx.y, d = threadIdx.x;  // blockDim = 64
    int s = g_gstart[g], e = g_gstart[g + 1];
    const float* base = feats + f * Nn * Dd;
    float s0 = 0.f, s1 = 0.f, s2 = 0.f, s3 = 0.f;
    int i = s;
    for (; i + 3 < e; i += 4) {
        s0 += base[i * Dd + d];
        s1 += base[(i + 1) * Dd + d];
        s2 += base[(i + 2) * Dd + d];
        s3 += base[(i + 3) * Dd + d];
    }
    for (; i < e; i++) s0 += base[i * Dd + d];
    float sum = (s0 + s1) + (s2 + s3);
    int cnt = e - s;
    if (cnt < 1) cnt = 1;
    out[(f * Gg + g) * Dd + d] = sum / (float)cnt;
}

// ---------------- host ----------------
extern "C" void kernel_launch(void* const* d_in, const int* in_sizes, int n_in,
                              void* d_out, int out_size) {
    const float* x     = (const float*)d_in[0];
    const int*   ei    = (const int*)d_in[1];
    const float* att   = (const float*)d_in[2];
    const int*   batch = (const int*)d_in[3];
    const float* lin_W = (const float*)d_in[4];
    const float* lin_b = (const float*)d_in[5];
    const float* Wrel  = (const float*)d_in[6];
    const float* brel  = (const float*)d_in[7];
    const float* Wroot = (const float*)d_in[8];
    const float* Wih   = (const float*)d_in[9];
    const float* Whh   = (const float*)d_in[10];
    const float* bih   = (const float*)d_in[11];
    const float* bhh   = (const float*)d_in[12];

    float* out = (float*)d_out;
    float* feats = out + NFf * Gg * Dd;
    const int* srcp = ei;
    const int* dstp = ei + Ee;

    int sm = 148;
    cudaDeviceGetAttribute(&sm, cudaDevAttrMultiProcessorCount, 0);
    int grid = (sm / 4) * 4;
    if (grid < 4) grid = 4;

    cudaFuncSetAttribute(k_layer, cudaFuncAttributeMaxDynamicSharedMemorySize, LAYER_SHM);
    cudaFuncSetAttribute(k_lin, cudaFuncAttributeMaxDynamicSharedMemorySize, LIN_SHM);

    void *pa, *pb;
    cudaGetSymbolAddress(&pa, g_stateA);
    cudaGetSymbolAddress(&pb, g_stateB);
    float* A = (float*)pa;
    float* B = (float*)pb;

    const int NB = (Nn + 1023) / 1024;

    k_zero<<<(Nn + 255) / 256, 256>>>();
    k_hist<<<(Ee + 255) / 256, 256>>>(dstp, batch);
    k_scan1<<<NB, 1024>>>();
    k_scan2<<<1, 32>>>(NB);
    k_scan3<<<NB, 1024>>>();
    k_scatter<<<(Ee + 255) / 256, 256>>>(srcp, dstp);
    k_sortseg<<<(Nn + 127) / 128, 128>>>();
    k_buildw<<<(Ee + 255) / 256, 256>>>(att);
    k_gscan<<<1, 32>>>();
    k_pack<<<(98304 + 255) / 256, 256>>>(Wrel, Wroot, Wih, Whh);

    k_lin<<<grid, 512, LIN_SHM>>>(x, lin_W, lin_b, A);
    k_layer<<<grid, 512, LAYER_SHM>>>(A, B, 0, brel, bih, bhh);
    k_layer<<<grid, 512, LAYER_SHM>>>(B, A, 1, brel, bih, bhh);
    k_layer<<<grid, 512, LAYER_SHM>>>(A, feats, 2, brel, bih, bhh);
    k_pool<<<dim3(Gg, NFf), 64>>>(feats, out);
}

// round 15
// speedup vs baseline: 1.0924x; 1.0000x over previous
#include <cuda_runtime.h>
#include <cuda_bf16.h>
#include <math.h>

typedef unsigned long long u64;
typedef unsigned int u32;

#define Nn 100000
#define Ee 1600000
#define Ff 128
#define NFf 4
#define Dd 64
#define NLl 3
#define Gg 128
#define NTILE 782   // ceil(Nn/128)

// ---------------- device scratch (no allocations allowed) ----------------
__device__ int   g_deg[Nn];
__device__ int   g_rowptr[Nn + 1];
__device__ int   g_fill[Nn];
__device__ int   g_bsums[256];
__device__ int   g_srcs[Ee];
__device__ int   g_eids[Ee];
__device__ float g_wcsr[NFf * Ee];
__device__ float g_stateA[NFf * Nn * Dd];
__device__ float g_stateB[NFf * Nn * Dd];
__device__ int   g_gcnt[Gg];
__device__ int   g_gstart[Gg + 1];
// fragment-packed bf16 weights (uint2 per lane-fragment) — R11 layout
__device__ uint2 g_pkconv[12 * 4096];   // [wl][mat:relH,relL,rootH,rootL][ks4][nt8][lane32]
__device__ uint2 g_pkgru[4 * 12288];    // [f][ihH2048,ihL2048,hhH2048,hhL2048,inH1024,inL1024,hnH1024,hnL1024]

// ---------------- helpers ----------------
__device__ __forceinline__ u64 ffma2(u64 a, u64 b, u64 c) {
    u64 d; asm("fma.rn.f32x2 %0,%1,%2,%3;" : "=l"(d) : "l"(a), "l"(b), "l"(c)); return d;
}
__device__ __forceinline__ u64 splat2(float v) {
    u64 d; u32 r = __float_as_uint(v);
    asm("mov.b64 %0,{%1,%2};" : "=l"(d) : "r"(r), "r"(r)); return d;
}
__device__ __forceinline__ float2 unpk(u64 v) {
    u32 lo, hi; asm("mov.b64 {%0,%1},%2;" : "=r"(lo), "=r"(hi) : "l"(v));
    return make_float2(__uint_as_float(lo), __uint_as_float(hi));
}
__device__ __forceinline__ float sigm(float v) { return 1.f / (1.f + __expf(-v)); }
__device__ __forceinline__ float tanh_f(float v) { return 2.f / (1.f + __expf(-2.f * v)) - 1.f; }

__device__ __forceinline__ u32 smem_u32(const void* p) {
    u32 a;
    asm("{ .reg .u64 t; cvta.to.shared.u64 t, %1; cvt.u32.u64 %0, t; }" : "=r"(a) : "l"(p));
    return a;
}

__device__ __forceinline__ void split2(float a0, float a1, u32& hi, u32& lo) {
    __nv_bfloat16 h0 = __float2bfloat16(a0), h1 = __float2bfloat16(a1);
    __nv_bfloat162 hp = __halves2bfloat162(h0, h1);
    float r0 = a0 - __bfloat162float(h0);
    float r1 = a1 - __bfloat162float(h1);
    __nv_bfloat162 lp = __floats2bfloat162_rn(r0, r1);
    hi = *(u32*)&hp; lo = *(u32*)&lp;
}

__device__ __forceinline__ u32 pkbf(float a, float b, bool lo) {
    __nv_bfloat16 ah = __float2bfloat16(a), bh = __float2bfloat16(b);
    if (lo) {
        ah = __float2bfloat16(a - __bfloat162float(ah));
        bh = __float2bfloat16(b - __bfloat162float(bh));
    }
    __nv_bfloat162 p = __halves2bfloat162(ah, bh);
    return *(u32*)&p;
}

__device__ __forceinline__ uint4 ldm(u32 addr) {
    uint4 r;
    asm volatile("ldmatrix.sync.aligned.m8n8.x4.shared.b16 {%0,%1,%2,%3}, [%4];"
        : "=r"(r.x), "=r"(r.y), "=r"(r.z), "=r"(r.w) : "r"(addr));
    return r;
}
__device__ __forceinline__ void mmaf(float d[4], uint4 a, uint2 b) {
    asm volatile("mma.sync.aligned.m16n8k16.row.col.f32.bf16.bf16.f32 "
        "{%0,%1,%2,%3}, {%4,%5,%6,%7}, {%8,%9}, {%0,%1,%2,%3};"
        : "+f"(d[0]), "+f"(d[1]), "+f"(d[2]), "+f"(d[3])
        : "r"(a.x), "r"(a.y), "r"(a.z), "r"(a.w), "r"(b.x), "r"(b.y));
}

// ---------------- CSR build ----------------
__global__ void k_zero() {
    int i = blockIdx.x * blockDim.x + threadIdx.x;
    if (i < Nn) g_deg[i] = 0;
    if (i < Gg) g_gcnt[i] = 0;
}

__global__ void k_hist(const int* __restrict__ dst, const int* __restrict__ batch) {
    int i = blockIdx.x * blockDim.x + threadIdx.x;
    if (i < Ee) atomicAdd(&g_deg[dst[i]], 1);
    if (i < Nn) atomicAdd(&g_gcnt[batch[i]], 1);
}

__global__ void k_scan1() {
    __shared__ int tmp[1024];
    int i = blockIdx.x * 1024 + threadIdx.x;
    int v = (i < Nn) ? g_deg[i] : 0;
    tmp[threadIdx.x] = v;
    __syncthreads();
    for (int off = 1; off < 1024; off <<= 1) {
        int t = 0;
        if (threadIdx.x >= off) t = tmp[threadIdx.x - off];
        __syncthreads();
        if (threadIdx.x >= off) tmp[threadIdx.x] += t;
        __syncthreads();
    }
    if (i < Nn) g_rowptr[i + 1] = tmp[threadIdx.x];
    if (threadIdx.x == 1023) g_bsums[blockIdx.x] = tmp[1023];
}

__global__ void k_scan2(int nb) {
    if (threadIdx.x == 0 && blockIdx.x == 0) {
        int run = 0;
        for (int b = 0; b < nb; b++) { int v = g_bsums[b]; g_bsums[b] = run; run += v; }
    }
}

__global__ void k_scan3() {
    int i = blockIdx.x * 1024 + threadIdx.x;
    if (i < Nn) {
        int v = g_rowptr[i + 1] + g_bsums[blockIdx.x];
        g_rowptr[i + 1] = v;
        if (i + 1 < Nn) g_fill[i + 1] = v;
    }
    if (i == 0) { g_rowptr[0] = 0; g_fill[0] = 0; }
}

__global__ void k_scatter(const int* __restrict__ src, const int* __restrict__ dst) {
    int e = blockIdx.x * blockDim.x + threadIdx.x;
    if (e < Ee) {
        int d = dst[e];
        int p = atomicAdd(&g_fill[d], 1);
        g_srcs[p] = src[e];
        g_eids[p] = e;
    }
}

__global__ void k_sortseg() {
    int n = blockIdx.x * blockDim.x + threadIdx.x;
    if (n >= Nn) return;
    int b = g_rowptr[n], e = g_rowptr[n + 1];
    for (int i = b + 1; i < e; i++) {
        int ke = g_eids[i], ks = g_srcs[i];
        int j = i - 1;
        while (j >= b && g_eids[j] > ke) {
            g_eids[j + 1] = g_eids[j];
            g_srcs[j + 1] = g_srcs[j];
            j--;
        }
        g_eids[j + 1] = ke;
        g_srcs[j + 1] = ks;
    }
}

__global__ void k_buildw(const float* __restrict__ att) {
    int j = blockIdx.x * blockDim.x + threadIdx.x;
    if (j < Ee) {
        int e = g_eids[j];
#pragma unroll
        for (int f = 0; f < NFf; f++) g_wcsr[f * Ee + j] = att[f * Ee + e];
    }
}

__global__ void k_gscan() {
    if (threadIdx.x == 0 && blockIdx.x == 0) {
        int run = 0;
        for (int g = 0; g < Gg; g++) { g_gstart[g] = run; run += g_gcnt[g]; }
        g_gstart[Gg] = run;
    }
}

// ---------------- weight pre-pack (R11 layout, unchanged) ----------------
__global__ void k_pack(const float* __restrict__ Wrel, const float* __restrict__ Wroot,
                       const float* __restrict__ Wih, const float* __restrict__ Whh) {
    int i = blockIdx.x * blockDim.x + threadIdx.x;
    if (i >= 98304) return;
    float v00, v01, v10, v11;
    bool lo;
    uint2* dst;
    if (i < 49152) {
        int wl = i >> 12;
        int r = i & 4095;
        int mat = r >> 10;          // 0 relH, 1 relL, 2 rootH, 3 rootL
        int fr = r & 1023;
        int ks = fr >> 8, nt = (fr >> 5) & 7, lane = fr & 31;
        int s = lane & 3, n = nt * 8 + (lane >> 2);
        int k0 = ks * 16 + 2 * s;
        const float* Wm = ((mat >= 2) ? Wroot : Wrel) + wl * 4096;  // B[k][n] = W[k*64+n]
        v00 = Wm[k0 * 64 + n];       v01 = Wm[(k0 + 1) * 64 + n];
        v10 = Wm[(k0 + 8) * 64 + n]; v11 = Wm[(k0 + 9) * 64 + n];
        lo = (mat & 1);
        dst = g_pkconv + i;
    } else {
        int j = i - 49152;
        int f = j / 12288;
        int r = j % 12288;
        const float* WI = Wih + f * 12288;
        const float* WH = Whh + f * 12288;
        if (r < 8192) {             // rz: ihH, ihL, hhH, hhL
            int mat = r >> 11;
            int fr = r & 2047;
            int ks = fr >> 9, nt = (fr >> 5) & 15, lane = fr & 31;
            int s = lane & 3, n = nt * 8 + (lane >> 2);
            int k0 = ks * 16 + 2 * s;
            const float* Wm = (mat >= 2) ? WH : WI;        // B[k][n] = W[n*64+k]
            v00 = Wm[n * 64 + k0];     v01 = Wm[n * 64 + k0 + 1];
            v10 = Wm[n * 64 + k0 + 8]; v11 = Wm[n * 64 + k0 + 9];
            lo = (mat & 1);
        } else {                    // n gate: inH, inL, hnH, hnL
            int rn = r - 8192;
            int mat = rn >> 10;
            int fr = rn & 1023;
            int ks = fr >> 8, nt = (fr >> 5) & 7, lane = fr & 31;
            int s = lane & 3, n = nt * 8 + (lane >> 2);
            int k0 = ks * 16 + 2 * s;
            const float* Wm = (mat >= 2) ? WH : WI;        // B[k][n] = W[(128+n)*64+k]
            v00 = Wm[(128 + n) * 64 + k0];     v01 = Wm[(128 + n) * 64 + k0 + 1];
            v10 = Wm[(128 + n) * 64 + k0 + 8]; v11 = Wm[(128 + n) * 64 + k0 + 9];
            lo = (mat & 1);
        }
        dst = g_pkgru + j;
    }
    *dst = make_uint2(pkbf(v00, v01, lo), pkbf(v10, v11, lo));
}

// ---------------- lin (FFMA champion, unchanged) ----------------
#define LIN_SHM ((8192 + 64 + 16 * 1280) * 4)
__global__ __launch_bounds__(512, 1) void k_lin(const float* __restrict__ x,
                                                const float* __restrict__ W_all,
                                                const float* __restrict__ b_all,
                                                float* __restrict__ out_base) {
    extern __shared__ float sh[];
    float* sW = sh;
    float* sb = sW + 8192;
    float* sX = sb + 64;
    int f = blockIdx.x & 3;
    int fslot = blockIdx.x >> 2;
    int nslot = gridDim.x >> 2;
    const float* W = W_all + f * Ff * Dd;
    const float* b = b_all + f * Dd;
    float* out = out_base + f * Nn * Dd;

    int tid = threadIdx.x;
    for (int i = tid; i < 8192; i += 512) sW[i] = W[i];
    if (tid < 64) sb[tid] = b[tid];
    __syncthreads();
    int warp = tid >> 5, lane = tid & 31;
    int d0 = 2 * lane;
    int nt = lane >> 2, cg = lane & 3;
    float* sXw = sX + warp * 1280;
    float bc0 = sb[d0], bc1 = sb[d0 + 1];

    for (int t = fslot; t < NTILE; t += nslot) {
        int n0 = t * 128 + warp * 8;
        if (n0 >= Nn) continue;
        {
            int n = n0 + nt;
            bool v = n < Nn;
            const float4* xr = (const float4*)(x + (v ? n : 0) * Ff) + cg * 8;
#pragma unroll
            for (int q = 0; q < 8; q++) {
                float4 tv = v ? xr[q] : make_float4(0, 0, 0, 0);
                int c = cg * 32 + q * 4;
                sXw[(c + 0) * 10 + nt] = tv.x;
                sXw[(c + 1) * 10 + nt] = tv.y;
                sXw[(c + 2) * 10 + nt] = tv.z;
                sXw[(c + 3) * 10 + nt] = tv.w;
            }
        }
        __syncwarp();
        u64 acc[4][2];
#pragma unroll
        for (int p = 0; p < 4; p++) { acc[p][0] = 0ull; acc[p][1] = 0ull; }
#pragma unroll 4
        for (int k = 0; k < Ff; k++) {
            float2 w = *(const float2*)(sW + k * 64 + d0);
            u64 sw0 = splat2(w.x), sw1 = splat2(w.y);
            const u64* xp = (const u64*)(sXw + k * 10);
#pragma unroll
            for (int p = 0; p < 4; p++) {
                u64 xv = xp[p];
                acc[p][0] = ffma2(xv, sw0, acc[p][0]);
                acc[p][1] = ffma2(xv, sw1, acc[p][1]);
            }
        }
#pragma unroll
        for (int p = 0; p < 4; p++) {
            float2 a0 = unpk(acc[p][0]), a1 = unpk(acc[p][1]);
            int na = n0 + 2 * p, nb = na + 1;
            if (na < Nn) *(float2*)(out + na * 64 + d0) = make_float2(a0.x + bc0, a1.x + bc1);
            if (nb < Nn) *(float2*)(out + nb * 64 + d0) = make_float2(a0.y + bc0, a1.y + bc1);
        }
        __syncwarp();
    }
}

// ---------------- fused layer: mma.sync bf16 (R11 base, A-frag reuse) ----------------
#define SM_AGH 0
#define SM_AGL 18432
#define SM_HH  36864
#define SM_HL  55296
#define SM_CONV 73728        // relH 8K, relL 8K, rootH 8K, rootL 8K
#define SM_GRU  106496       // ihH 16K, ihL 16K, hhH 16K, hhL 16K, inH 8K, inL 8K, hnH 8K, hnL 8K
#define SM_BREL 204800
#define SM_BIH  205056
#define SM_BHH  205824
#define LAYER_SHM 206592

// 4 MMAs against an 8-nt-block B matrix (conv / n-gate layout)
#define MM4(ACC, A, BOFF) do { \
    const uint2* _b = (const uint2*)(sm + (BOFF)); \
    _Pragma("unroll") \
    for (int j = 0; j < 4; j++) \
        mmaf(ACC[j], A, _b[(ks * 8 + nh * 4 + j) * 32 + lane]); \
} while (0)

// 8 MMAs against the 16-nt-block rz B matrix
#define MMRZ(A, BOFF) do { \
    const uint2* _b = (const uint2*)(sm + (BOFF)); \
    _Pragma("unroll") \
    for (int j = 0; j < 4; j++) \
        mmaf(accRZ[j], A, _b[(ks * 16 + nh * 4 + j) * 32 + lane]); \
    _Pragma("unroll") \
    for (int j = 0; j < 4; j++) \
        mmaf(accRZ[4 + j], A, _b[(ks * 16 + 8 + nh * 4 + j) * 32 + lane]); \
} while (0)

__global__ __launch_bounds__(512, 1) void k_layer(const float* __restrict__ in_base,
                                                  float* __restrict__ out_base,
                                                  int layer,
                                                  const float* __restrict__ brel_all,
                                                  const float* __restrict__ bih_all,
                                                  const float* __restrict__ bhh_all) {
    extern __shared__ unsigned char sm[];
    u32 smb = smem_u32(sm);
    int tid = threadIdx.x, warp = tid >> 5, lane = tid & 31;
    int f = blockIdx.x & 3;
    int fslot = blockIdx.x >> 2;
    int nslot = gridDim.x >> 2;
    int wl = f * NLl + layer;
    const float* in_state = in_base + f * Nn * Dd;
    float* out_state = out_base + f * Nn * Dd;
    const float* wfp = g_wcsr + f * Ee;

    {   // weights + biases -> smem
        const uint4* pc = (const uint4*)(g_pkconv + wl * 4096);
        uint4* dc = (uint4*)(sm + SM_CONV);
        for (int i = tid; i < 2048; i += 512) dc[i] = pc[i];
        const uint4* pg = (const uint4*)(g_pkgru + f * 12288);
        uint4* dg = (uint4*)(sm + SM_GRU);
        for (int i = tid; i < 6144; i += 512) dg[i] = pg[i];
        float* sb = (float*)(sm + SM_BREL);
        if (tid < 64) sb[tid] = brel_all[wl * 64 + tid];
        float* si = (float*)(sm + SM_BIH);
        float* shh = (float*)(sm + SM_BHH);
        if (tid < 192) { si[tid] = bih_all[f * 192 + tid]; shh[tid] = bhh_all[f * 192 + tid]; }
    }
    __syncthreads();

    int mt = warp >> 1, nh = warp & 1;
    int g = lane >> 2, s = lane & 3;
    u32 aoff = (u32)((mt * 16 + (lane & 15)) * 144 + (lane >> 4) * 16);
    int nl = tid >> 2, cg = tid & 3;
    const float* sbrel = (const float*)(sm + SM_BREL);
    const float* sbih  = (const float*)(sm + SM_BIH);
    const float* sbhh  = (const float*)(sm + SM_BHH);

    for (int t = fslot; t < NTILE; t += nslot) {
        int n0 = t * 128;

        // ---- stage: agg (fp32) + h -> bf16 hi/lo tiles ----
        {
            int gn = n0 + nl;
            bool v = gn < Nn;
            float hv[16], acc[16];
            const float4* hr = (const float4*)(in_state + (v ? gn : 0) * 64 + cg * 16);
#pragma unroll
            for (int q = 0; q < 4; q++) {
                float4 tv = v ? hr[q] : make_float4(0, 0, 0, 0);
                hv[4 * q] = tv.x; hv[4 * q + 1] = tv.y; hv[4 * q + 2] = tv.z; hv[4 * q + 3] = tv.w;
            }
#pragma unroll
            for (int ii = 0; ii < 16; ii++) acc[ii] = 0.f;
            if (v) {
                int beg = g_rowptr[gn], end = g_rowptr[gn + 1];
                for (int j = beg; j < end; j++) {
                    int sn = g_srcs[j];
                    float w = wfp[j];
                    const float4* sr = (const float4*)(in_state + sn * 64 + cg * 16);
#pragma unroll
                    for (int q = 0; q < 4; q++) {
                        float4 tv = sr[q];
                        acc[4 * q] += w * tv.x; acc[4 * q + 1] += w * tv.y;
                        acc[4 * q + 2] += w * tv.z; acc[4 * q + 3] += w * tv.w;
                    }
                }
            }
#pragma unroll
            for (int ii = 0; ii < 8; ii++) {
                int c = cg * 16 + 2 * ii;
                u32 off = (u32)(nl * 144 + c * 2);
                u32 hi, lo;
                split2(acc[2 * ii], acc[2 * ii + 1], hi, lo);
                *(u32*)(sm + SM_AGH + off) = hi;
                *(u32*)(sm + SM_AGL + off) = lo;
                split2(hv[2 * ii], hv[2 * ii + 1], hi, lo);
                *(u32*)(sm + SM_HH + off) = hi;
                *(u32*)(sm + SM_HL + off) = lo;
            }
        }
        __syncthreads();

        // ---- Loop A: conv GEMM + hn GEMM (A-major; HH/HL frags shared) ----
        float accC[4][4], accH[4][4];
#pragma unroll
        for (int a = 0; a < 4; a++)
#pragma unroll
            for (int b = 0; b < 4; b++) { accC[a][b] = 0.f; accH[a][b] = 0.f; }
#pragma unroll
        for (int ks = 0; ks < 4; ks++) {
            uint4 a = ldm(smb + SM_AGH + aoff + ks * 32);
            MM4(accC, a, SM_CONV);              // agg(hi) @ rel(hi)
            MM4(accC, a, SM_CONV + 8192);       // agg(hi) @ rel(lo)
            a = ldm(smb + SM_AGL + aoff + ks * 32);
            MM4(accC, a, SM_CONV);              // agg(lo) @ rel(hi)
            a = ldm(smb + SM_HH + aoff + ks * 32);
            MM4(accC, a, SM_CONV + 16384);      // h(hi) @ root(hi)
            MM4(accC, a, SM_CONV + 24576);      // h(hi) @ root(lo)
            MM4(accH, a, SM_GRU + 81920);       // h(hi) @ hn(hi)
            MM4(accH, a, SM_GRU + 90112);       // h(hi) @ hn(lo)
            a = ldm(smb + SM_HL + aoff + ks * 32);
            MM4(accC, a, SM_CONV + 16384);      // h(lo) @ root(hi)
            MM4(accH, a, SM_GRU + 81920);       // h(lo) @ hn(hi)
        }
        __syncthreads();

        // ---- epilogue 1: m = relu(conv + brel) -> overwrite agg tiles ----
        {
#pragma unroll
            for (int j = 0; j < 4; j++) {
                int c = nh * 32 + j * 8 + 2 * s;
                u32 off = (u32)((mt * 16 + g) * 144 + c * 2);
                u32 hi, lo;
                float m0 = fmaxf(accC[j][0] + sbrel[c], 0.f);
                float m1 = fmaxf(accC[j][1] + sbrel[c + 1], 0.f);
                split2(m0, m1, hi, lo);
                *(u32*)(sm + SM_AGH + off) = hi;
                *(u32*)(sm + SM_AGL + off) = lo;
                m0 = fmaxf(accC[j][2] + sbrel[c], 0.f);
                m1 = fmaxf(accC[j][3] + sbrel[c + 1], 0.f);
                split2(m0, m1, hi, lo);
                *(u32*)(sm + SM_AGH + off + 8 * 144) = hi;
                *(u32*)(sm + SM_AGL + off + 8 * 144) = lo;
            }
        }
        __syncthreads();

        // ---- Loop B: rz GEMM + in GEMM (A-major) ----
        float accRZ[8][4], accI[4][4];
#pragma unroll
        for (int a = 0; a < 8; a++)
#pragma unroll
            for (int b = 0; b < 4; b++) accRZ[a][b] = 0.f;
#pragma unroll
        for (int a = 0; a < 4; a++)
#pragma unroll
            for (int b = 0; b < 4; b++) accI[a][b] = 0.f;
#pragma unroll
        for (int ks = 0; ks < 4; ks++) {
            uint4 a = ldm(smb + SM_AGH + aoff + ks * 32);
            MMRZ(a, SM_GRU);                    // m(hi) @ ih(hi)
            MMRZ(a, SM_GRU + 16384);            // m(hi) @ ih(lo)
            MM4(accI, a, SM_GRU + 65536);       // m(hi) @ in(hi)
            MM4(accI, a, SM_GRU + 73728);       // m(hi) @ in(lo)
            a = ldm(smb + SM_AGL + aoff + ks * 32);
            MMRZ(a, SM_GRU);                    // m(lo) @ ih(hi)
            MM4(accI, a, SM_GRU + 65536);       // m(lo) @ in(hi)
            a = ldm(smb + SM_HH + aoff + ks * 32);
            MMRZ(a, SM_GRU + 32768);            // h(hi) @ hh(hi)
            MMRZ(a, SM_GRU + 49152);            // h(hi) @ hh(lo)
            a = ldm(smb + SM_HL + aoff + ks * 32);
            MMRZ(a, SM_GRU + 32768);            // h(lo) @ hh(hi)
        }

        // ---- epilogue 2: gates + blend + store (register-resident) ----
        {
#pragma unroll
            for (int j = 0; j < 4; j++) {
                int c = nh * 32 + j * 8 + 2 * s;
#pragma unroll
                for (int q = 0; q < 2; q++) {
                    int row = mt * 16 + g + q * 8;
                    int gn = n0 + row;
                    if (gn < Nn) {
                        float r0v = sigm(accRZ[j][2 * q]     + sbih[c]     + sbhh[c]);
                        float r1v = sigm(accRZ[j][2 * q + 1] + sbih[c + 1] + sbhh[c + 1]);
                        float z0v = sigm(accRZ[4 + j][2 * q]     + sbih[64 + c]     + sbhh[64 + c]);
                        float z1v = sigm(accRZ[4 + j][2 * q + 1] + sbih[64 + c + 1] + sbhh[64 + c + 1]);
                        float nn0 = tanh_f(accI[j][2 * q]     + sbih[128 + c]     + r0v * (accH[j][2 * q]     + sbhh[128 + c]));
                        float nn1 = tanh_f(accI[j][2 * q + 1] + sbih[128 + c + 1] + r1v * (accH[j][2 * q + 1] + sbhh[128 + c + 1]));
                        float2 hp = *(const float2*)(in_state + gn * 64 + c);
                        float o0 = (1.f - z0v) * nn0 + z0v * hp.x;
                        float o1 = (1.f - z1v) * nn1 + z1v * hp.y;
                        *(float2*)(out_state + gn * 64 + c) = make_float2(o0, o1);
                    }
                }
            }
        }
        __syncthreads();
    }
}

// ---------------- global mean pool ----------------
__global__ void k_pool(const float* __restrict__ feats, float* __restrict__ out) {
    int g = blockIdx.x, f = blockIdx.y, d = threadIdx.x;  // blockDim = 64
    int s = g_gstart[g], e = g_gstart[g + 1];
    const float* base = feats + f * Nn * Dd;
    float s0 = 0.f, s1 = 0.f, s2 = 0.f, s3 = 0.f;
    int i = s;
    for (; i + 3 < e; i += 4) {
        s0 += base[i * Dd + d];
        s1 += base[(i + 1) * Dd + d];
        s2 += base[(i + 2) * Dd + d];
        s3 += base[(i + 3) * Dd + d];
    }
    for (; i < e; i++) s0 += base[i * Dd + d];
    float sum = (s0 + s1) + (s2 + s3);
    int cnt = e - s;
    if (cnt < 1) cnt = 1;
    out[(f * Gg + g) * Dd + d] = sum / (float)cnt;
}

// ---------------- host ----------------
extern "C" void kernel_launch(void* const* d_in, const int* in_sizes, int n_in,
                              void* d_out, int out_size) {
    const float* x     = (const float*)d_in[0];
    const int*   ei    = (const int*)d_in[1];
    const float* att   = (const float*)d_in[2];
    const int*   batch = (const int*)d_in[3];
    const float* lin_W = (const float*)d_in[4];
    const float* lin_b = (const float*)d_in[5];
    const float* Wrel  = (const float*)d_in[6];
    const float* brel  = (const float*)d_in[7];
    const float* Wroot = (const float*)d_in[8];
    const float* Wih   = (const float*)d_in[9];
    const float* Whh   = (const float*)d_in[10];
    const float* bih   = (const float*)d_in[11];
    const float* bhh   = (const float*)d_in[12];

    float* out = (float*)d_out;
    float* feats = out + NFf * Gg * Dd;
    const int* srcp = ei;
    const int* dstp = ei + Ee;

    int sm = 148;
    cudaDeviceGetAttribute(&sm, cudaDevAttrMultiProcessorCount, 0);
    int grid = (sm / 4) * 4;
    if (grid < 4) grid = 4;

    cudaFuncSetAttribute(k_layer, cudaFuncAttributeMaxDynamicSharedMemorySize, LAYER_SHM);
    cudaFuncSetAttribute(k_lin, cudaFuncAttributeMaxDynamicSharedMemorySize, LIN_SHM);

    void *pa, *pb;
    cudaGetSymbolAddress(&pa, g_stateA);
    cudaGetSymbolAddress(&pb, g_stateB);
    float* A = (float*)pa;
    float* B = (float*)pb;

    const int NB = (Nn + 1023) / 1024;

    k_zero<<<(Nn + 255) / 256, 256>>>();
    k_hist<<<(Ee + 255) / 256, 256>>>(dstp, batch);
    k_scan1<<<NB, 1024>>>();
    k_scan2<<<1, 32>>>(NB);
    k_scan3<<<NB, 1024>>>();
    k_scatter<<<(Ee + 255) / 256, 256>>>(srcp, dstp);
    k_sortseg<<<(Nn + 127) / 128, 128>>>();
    k_buildw<<<(Ee + 255) / 256, 256>>>(att);
    k_gscan<<<1, 32>>>();
    k_pack<<<(98304 + 255) / 256, 256>>>(Wrel, Wroot, Wih, Whh);

    k_lin<<<grid, 512, LIN_SHM>>>(x, lin_W, lin_b, A);
    k_layer<<<grid, 512, LAYER_SHM>>>(A, B, 0, brel, bih, bhh);
    k_layer<<<grid, 512, LAYER_SHM>>>(B, A, 1, brel, bih, bhh);
    k_layer<<<grid, 512, LAYER_SHM>>>(A, feats, 2, brel, bih, bhh);
    k_pool<<<dim3(Gg, NFf), 64>>>(feats, out);
}

// round 16
// speedup vs baseline: 1.2376x; 1.1330x over previous
#include <cuda_runtime.h>
#include <cuda_bf16.h>
#include <math.h>

typedef unsigned long long u64;
typedef unsigned int u32;

#define Nn 100000
#define Ee 1600000
#define Ff 128
#define NFf 4
#define Dd 64
#define NLl 3
#define Gg 128
#define NTILE 782    // ceil(Nn/128) for k_lin
#define NT64 1563    // ceil(Nn/64) for k_layer

// ---------------- device scratch (no allocations allowed) ----------------
__device__ int   g_deg[Nn];
__device__ int   g_rowptr[Nn + 1];
__device__ int   g_fill[Nn];
__device__ int   g_bsums[256];
__device__ int   g_srcs[Ee];
__device__ int   g_eids[Ee];
__device__ float g_wcsr[NFf * Ee];
__device__ float g_stateA[NFf * Nn * Dd];
__device__ float g_stateB[NFf * Nn * Dd];
__device__ int   g_gcnt[Gg];
__device__ int   g_gstart[Gg + 1];
// fragment-packed bf16 weights (uint2 per lane-fragment) — R11 layout
__device__ uint2 g_pkconv[12 * 4096];
__device__ uint2 g_pkgru[4 * 12288];

// ---------------- helpers ----------------
__device__ __forceinline__ u64 ffma2(u64 a, u64 b, u64 c) {
    u64 d; asm("fma.rn.f32x2 %0,%1,%2,%3;" : "=l"(d) : "l"(a), "l"(b), "l"(c)); return d;
}
__device__ __forceinline__ u64 splat2(float v) {
    u64 d; u32 r = __float_as_uint(v);
    asm("mov.b64 %0,{%1,%2};" : "=l"(d) : "r"(r), "r"(r)); return d;
}
__device__ __forceinline__ float2 unpk(u64 v) {
    u32 lo, hi; asm("mov.b64 {%0,%1},%2;" : "=r"(lo), "=r"(hi) : "l"(v));
    return make_float2(__uint_as_float(lo), __uint_as_float(hi));
}
__device__ __forceinline__ float sigm(float v) { return 1.f / (1.f + __expf(-v)); }
__device__ __forceinline__ float tanh_f(float v) { return 2.f / (1.f + __expf(-2.f * v)) - 1.f; }

__device__ __forceinline__ u32 smem_u32(const void* p) {
    u32 a;
    asm("{ .reg .u64 t; cvta.to.shared.u64 t, %1; cvt.u32.u64 %0, t; }" : "=r"(a) : "l"(p));
    return a;
}

__device__ __forceinline__ void split2(float a0, float a1, u32& hi, u32& lo) {
    __nv_bfloat16 h0 = __float2bfloat16(a0), h1 = __float2bfloat16(a1);
    __nv_bfloat162 hp = __halves2bfloat162(h0, h1);
    float r0 = a0 - __bfloat162float(h0);
    float r1 = a1 - __bfloat162float(h1);
    __nv_bfloat162 lp = __floats2bfloat162_rn(r0, r1);
    hi = *(u32*)&hp; lo = *(u32*)&lp;
}

__device__ __forceinline__ u32 pkbf(float a, float b, bool lo) {
    __nv_bfloat16 ah = __float2bfloat16(a), bh = __float2bfloat16(b);
    if (lo) {
        ah = __float2bfloat16(a - __bfloat162float(ah));
        bh = __float2bfloat16(b - __bfloat162float(bh));
    }
    __nv_bfloat162 p = __halves2bfloat162(ah, bh);
    return *(u32*)&p;
}

__device__ __forceinline__ uint4 ldm(u32 addr) {
    uint4 r;
    asm volatile("ldmatrix.sync.aligned.m8n8.x4.shared.b16 {%0,%1,%2,%3}, [%4];"
        : "=r"(r.x), "=r"(r.y), "=r"(r.z), "=r"(r.w) : "r"(addr));
    return r;
}
__device__ __forceinline__ void mmaf(float d[4], uint4 a, uint2 b) {
    asm volatile("mma.sync.aligned.m16n8k16.row.col.f32.bf16.bf16.f32 "
        "{%0,%1,%2,%3}, {%4,%5,%6,%7}, {%8,%9}, {%0,%1,%2,%3};"
        : "+f"(d[0]), "+f"(d[1]), "+f"(d[2]), "+f"(d[3])
        : "r"(a.x), "r"(a.y), "r"(a.z), "r"(a.w), "r"(b.x), "r"(b.y));
}

#define BAR_SYNC(id, cnt)   asm volatile("bar.sync %0, %1;"   :: "r"(id), "r"(cnt) : "memory")
#define BAR_ARRIVE(id, cnt) asm volatile("bar.arrive %0, %1;" :: "r"(id), "r"(cnt) : "memory")

// ---------------- CSR build ----------------
__global__ void k_zero() {
    int i = blockIdx.x * blockDim.x + threadIdx.x;
    if (i < Nn) g_deg[i] = 0;
    if (i < Gg) g_gcnt[i] = 0;
}

__global__ void k_hist(const int* __restrict__ dst, const int* __restrict__ batch) {
    int i = blockIdx.x * blockDim.x + threadIdx.x;
    if (i < Ee) atomicAdd(&g_deg[dst[i]], 1);
    if (i < Nn) atomicAdd(&g_gcnt[batch[i]], 1);
}

__global__ void k_scan1() {
    __shared__ int tmp[1024];
    int i = blockIdx.x * 1024 + threadIdx.x;
    int v = (i < Nn) ? g_deg[i] : 0;
    tmp[threadIdx.x] = v;
    __syncthreads();
    for (int off = 1; off < 1024; off <<= 1) {
        int t = 0;
        if (threadIdx.x >= off) t = tmp[threadIdx.x - off];
        __syncthreads();
        if (threadIdx.x >= off) tmp[threadIdx.x] += t;
        __syncthreads();
    }
    if (i < Nn) g_rowptr[i + 1] = tmp[threadIdx.x];
    if (threadIdx.x == 1023) g_bsums[blockIdx.x] = tmp[1023];
}

__global__ void k_scan2(int nb) {
    if (threadIdx.x == 0 && blockIdx.x == 0) {
        int run = 0;
        for (int b = 0; b < nb; b++) { int v = g_bsums[b]; g_bsums[b] = run; run += v; }
    }
}

__global__ void k_scan3() {
    int i = blockIdx.x * 1024 + threadIdx.x;
    if (i < Nn) {
        int v = g_rowptr[i + 1] + g_bsums[blockIdx.x];
        g_rowptr[i + 1] = v;
        if (i + 1 < Nn) g_fill[i + 1] = v;
    }
    if (i == 0) { g_rowptr[0] = 0; g_fill[0] = 0; }
}

__global__ void k_scatter(const int* __restrict__ src, const int* __restrict__ dst) {
    int e = blockIdx.x * blockDim.x + threadIdx.x;
    if (e < Ee) {
        int d = dst[e];
        int p = atomicAdd(&g_fill[d], 1);
        g_srcs[p] = src[e];
        g_eids[p] = e;
    }
}

__global__ void k_sortseg() {
    int n = blockIdx.x * blockDim.x + threadIdx.x;
    if (n >= Nn) return;
    int b = g_rowptr[n], e = g_rowptr[n + 1];
    for (int i = b + 1; i < e; i++) {
        int ke = g_eids[i], ks = g_srcs[i];
        int j = i - 1;
        while (j >= b && g_eids[j] > ke) {
            g_eids[j + 1] = g_eids[j];
            g_srcs[j + 1] = g_srcs[j];
            j--;
        }
        g_eids[j + 1] = ke;
        g_srcs[j + 1] = ks;
    }
}

__global__ void k_buildw(const float* __restrict__ att) {
    int j = blockIdx.x * blockDim.x + threadIdx.x;
    if (j < Ee) {
        int e = g_eids[j];
#pragma unroll
        for (int f = 0; f < NFf; f++) g_wcsr[f * Ee + j] = att[f * Ee + e];
    }
}

__global__ void k_gscan() {
    if (threadIdx.x == 0 && blockIdx.x == 0) {
        int run = 0;
        for (int g = 0; g < Gg; g++) { g_gstart[g] = run; run += g_gcnt[g]; }
        g_gstart[Gg] = run;
    }
}

// ---------------- weight pre-pack (R11 layout, unchanged) ----------------
__global__ void k_pack(const float* __restrict__ Wrel, const float* __restrict__ Wroot,
                       const float* __restrict__ Wih, const float* __restrict__ Whh) {
    int i = blockIdx.x * blockDim.x + threadIdx.x;
    if (i >= 98304) return;
    float v00, v01, v10, v11;
    bool lo;
    uint2* dst;
    if (i < 49152) {
        int wl = i >> 12;
        int r = i & 4095;
        int mat = r >> 10;
        int fr = r & 1023;
        int ks = fr >> 8, nt = (fr >> 5) & 7, lane = fr & 31;
        int s = lane & 3, n = nt * 8 + (lane >> 2);
        int k0 = ks * 16 + 2 * s;
        const float* Wm = ((mat >= 2) ? Wroot : Wrel) + wl * 4096;
        v00 = Wm[k0 * 64 + n];       v01 = Wm[(k0 + 1) * 64 + n];
        v10 = Wm[(k0 + 8) * 64 + n]; v11 = Wm[(k0 + 9) * 64 + n];
        lo = (mat & 1);
        dst = g_pkconv + i;
    } else {
        int j = i - 49152;
        int f = j / 12288;
        int r = j % 12288;
        const float* WI = Wih + f * 12288;
        const float* WH = Whh + f * 12288;
        if (r < 8192) {
            int mat = r >> 11;
            int fr = r & 2047;
            int ks = fr >> 9, nt = (fr >> 5) & 15, lane = fr & 31;
            int s = lane & 3, n = nt * 8 + (lane >> 2);
            int k0 = ks * 16 + 2 * s;
            const float* Wm = (mat >= 2) ? WH : WI;
            v00 = Wm[n * 64 + k0];     v01 = Wm[n * 64 + k0 + 1];
            v10 = Wm[n * 64 + k0 + 8]; v11 = Wm[n * 64 + k0 + 9];
            lo = (mat & 1);
        } else {
            int rn = r - 8192;
            int mat = rn >> 10;
            int fr = rn & 1023;
            int ks = fr >> 8, nt = (fr >> 5) & 7, lane = fr & 31;
            int s = lane & 3, n = nt * 8 + (lane >> 2);
            int k0 = ks * 16 + 2 * s;
            const float* Wm = (mat >= 2) ? WH : WI;
            v00 = Wm[(128 + n) * 64 + k0];     v01 = Wm[(128 + n) * 64 + k0 + 1];
            v10 = Wm[(128 + n) * 64 + k0 + 8]; v11 = Wm[(128 + n) * 64 + k0 + 9];
            lo = (mat & 1);
        }
        dst = g_pkgru + j;
    }
    *dst = make_uint2(pkbf(v00, v01, lo), pkbf(v10, v11, lo));
}

// ---------------- lin (FFMA champion, unchanged) ----------------
#define LIN_SHM ((8192 + 64 + 16 * 1280) * 4)
__global__ __launch_bounds__(512, 1) void k_lin(const float* __restrict__ x,
                                                const float* __restrict__ W_all,
                                                const float* __restrict__ b_all,
                                                float* __restrict__ out_base) {
    extern __shared__ float sh[];
    float* sW = sh;
    float* sb = sW + 8192;
    float* sX = sb + 64;
    int f = blockIdx.x & 3;
    int fslot = blockIdx.x >> 2;
    int nslot = gridDim.x >> 2;
    const float* W = W_all + f * Ff * Dd;
    const float* b = b_all + f * Dd;
    float* out = out_base + f * Nn * Dd;

    int tid = threadIdx.x;
    for (int i = tid; i < 8192; i += 512) sW[i] = W[i];
    if (tid < 64) sb[tid] = b[tid];
    __syncthreads();
    int warp = tid >> 5, lane = tid & 31;
    int d0 = 2 * lane;
    int nt = lane >> 2, cg = lane & 3;
    float* sXw = sX + warp * 1280;
    float bc0 = sb[d0], bc1 = sb[d0 + 1];

    for (int t = fslot; t < NTILE; t += nslot) {
        int n0 = t * 128 + warp * 8;
        if (n0 >= Nn) continue;
        {
            int n = n0 + nt;
            bool v = n < Nn;
            const float4* xr = (const float4*)(x + (v ? n : 0) * Ff) + cg * 8;
#pragma unroll
            for (int q = 0; q < 8; q++) {
                float4 tv = v ? xr[q] : make_float4(0, 0, 0, 0);
                int c = cg * 32 + q * 4;
                sXw[(c + 0) * 10 + nt] = tv.x;
                sXw[(c + 1) * 10 + nt] = tv.y;
                sXw[(c + 2) * 10 + nt] = tv.z;
                sXw[(c + 3) * 10 + nt] = tv.w;
            }
        }
        __syncwarp();
        u64 acc[4][2];
#pragma unroll
        for (int p = 0; p < 4; p++) { acc[p][0] = 0ull; acc[p][1] = 0ull; }
#pragma unroll 4
        for (int k = 0; k < Ff; k++) {
            float2 w = *(const float2*)(sW + k * 64 + d0);
            u64 sw0 = splat2(w.x), sw1 = splat2(w.y);
            const u64* xp = (const u64*)(sXw + k * 10);
#pragma unroll
            for (int p = 0; p < 4; p++) {
                u64 xv = xp[p];
                acc[p][0] = ffma2(xv, sw0, acc[p][0]);
                acc[p][1] = ffma2(xv, sw1, acc[p][1]);
            }
        }
#pragma unroll
        for (int p = 0; p < 4; p++) {
            float2 a0 = unpk(acc[p][0]), a1 = unpk(acc[p][1]);
            int na = n0 + 2 * p, nb = na + 1;
            if (na < Nn) *(float2*)(out + na * 64 + d0) = make_float2(a0.x + bc0, a1.x + bc1);
            if (nb < Nn) *(float2*)(out + nb * 64 + d0) = make_float2(a0.y + bc0, a1.y + bc1);
        }
        __syncwarp();
    }
}

// ---------------- fused layer: warp-specialized producer/consumer, 64-node tiles ----------------
// double-buffered act tiles: buf b at b*36864; arrays AGH+0, AGL+9216, HH+18432, HL+27648
#define BUF_SZ  36864
#define OF_AGH  0
#define OF_AGL  9216
#define OF_HH   18432
#define OF_HL   27648
#define SM_CONV 73728
#define SM_GRU  106496
#define SM_BREL 204800
#define SM_BIH  205056
#define SM_BHH  205824
#define LAYER_SHM 206592

#define MM4(ACC, A, BOFF) do { \
    const uint2* _b = (const uint2*)(sm + (BOFF)); \
    _Pragma("unroll") \
    for (int j = 0; j < 4; j++) \
        mmaf(ACC[j], A, _b[(ks * 8 + nh * 4 + j) * 32 + lane]); \
} while (0)

#define MMRZ(A, BOFF) do { \
    const uint2* _b = (const uint2*)(sm + (BOFF)); \
    _Pragma("unroll") \
    for (int j = 0; j < 4; j++) \
        mmaf(accRZ[j], A, _b[(ks * 16 + nh * 4 + j) * 32 + lane]); \
    _Pragma("unroll") \
    for (int j = 0; j < 4; j++) \
        mmaf(accRZ[4 + j], A, _b[(ks * 16 + 8 + nh * 4 + j) * 32 + lane]); \
} while (0)

__global__ __launch_bounds__(512, 1) void k_layer(const float* __restrict__ in_base,
                                                  float* __restrict__ out_base,
                                                  int layer,
                                                  const float* __restrict__ brel_all,
                                                  const float* __restrict__ bih_all,
                                                  const float* __restrict__ bhh_all) {
    extern __shared__ unsigned char sm[];
    u32 smb = smem_u32(sm);
    int tid = threadIdx.x, warp = tid >> 5, lane = tid & 31;
    int f = blockIdx.x & 3;
    int fslot = blockIdx.x >> 2;
    int nslot = gridDim.x >> 2;
    int wl = f * NLl + layer;
    const float* in_state = in_base + f * Nn * Dd;
    float* out_state = out_base + f * Nn * Dd;
    const float* wfp = g_wcsr + f * Ee;

    {   // weights + biases -> smem (all 512 threads)
        const uint4* pc = (const uint4*)(g_pkconv + wl * 4096);
        uint4* dc = (uint4*)(sm + SM_CONV);
        for (int i = tid; i < 2048; i += 512) dc[i] = pc[i];
        const uint4* pg = (const uint4*)(g_pkgru + f * 12288);
        uint4* dg = (uint4*)(sm + SM_GRU);
        for (int i = tid; i < 6144; i += 512) dg[i] = pg[i];
        float* sb = (float*)(sm + SM_BREL);
        if (tid < 64) sb[tid] = brel_all[wl * 64 + tid];
        float* si = (float*)(sm + SM_BIH);
        float* shh = (float*)(sm + SM_BHH);
        if (tid < 192) { si[tid] = bih_all[f * 192 + tid]; shh[tid] = bhh_all[f * 192 + tid]; }
    }
    __syncthreads();

    if (warp >= 8) {
        // ================= PRODUCER (warps 8..15) =================
        int ptid = tid - 256;
        int nl = ptid >> 2, cg = ptid & 3;
        int i = 0;
        for (int t = fslot; t < NT64; t += nslot, i++) {
            int p = i & 1;
            u32 bb = (u32)(p * BUF_SZ);
            BAR_SYNC(3 + p, 512);            // wait buffer empty
            int gn = t * 64 + nl;
            bool v = gn < Nn;
            float hv[16], acc[16];
            const float4* hr = (const float4*)(in_state + (v ? gn : 0) * 64 + cg * 16);
#pragma unroll
            for (int q = 0; q < 4; q++) {
                float4 tv = v ? hr[q] : make_float4(0, 0, 0, 0);
                hv[4 * q] = tv.x; hv[4 * q + 1] = tv.y; hv[4 * q + 2] = tv.z; hv[4 * q + 3] = tv.w;
            }
#pragma unroll
            for (int ii = 0; ii < 16; ii++) acc[ii] = 0.f;
            if (v) {
                int beg = g_rowptr[gn], end = g_rowptr[gn + 1];
                for (int j = beg; j < end; j++) {
                    int sn = g_srcs[j];
                    float w = wfp[j];
                    const float4* sr = (const float4*)(in_state + sn * 64 + cg * 16);
#pragma unroll
                    for (int q = 0; q < 4; q++) {
                        float4 tv = sr[q];
                        acc[4 * q] += w * tv.x; acc[4 * q + 1] += w * tv.y;
                        acc[4 * q + 2] += w * tv.z; acc[4 * q + 3] += w * tv.w;
                    }
                }
            }
#pragma unroll
            for (int ii = 0; ii < 8; ii++) {
                int c = cg * 16 + 2 * ii;
                u32 off = bb + (u32)(nl * 144 + c * 2);
                u32 hi, lo;
                split2(acc[2 * ii], acc[2 * ii + 1], hi, lo);
                *(u32*)(sm + OF_AGH + off) = hi;
                *(u32*)(sm + OF_AGL + off) = lo;
                split2(hv[2 * ii], hv[2 * ii + 1], hi, lo);
                *(u32*)(sm + OF_HH + off) = hi;
                *(u32*)(sm + OF_HL + off) = lo;
            }
            BAR_ARRIVE(1 + p, 512);          // signal buffer full
        }
    } else {
        // ================= CONSUMER (warps 0..7) =================
        int mt = warp >> 1, nh = warp & 1;
        int g = lane >> 2, s = lane & 3;
        u32 aoff = (u32)((mt * 16 + (lane & 15)) * 144 + (lane >> 4) * 16);
        const float* sbrel = (const float*)(sm + SM_BREL);
        const float* sbih  = (const float*)(sm + SM_BIH);
        const float* sbhh  = (const float*)(sm + SM_BHH);

        BAR_ARRIVE(3, 512);                  // both buffers start empty
        BAR_ARRIVE(4, 512);

        int i = 0;
        for (int t = fslot; t < NT64; t += nslot, i++) {
            int p = i & 1;
            u32 bb = (u32)(p * BUF_SZ);
            int n0 = t * 64;
            BAR_SYNC(1 + p, 512);            // wait buffer full

            // ---- Loop A: conv + hn GEMMs ----
            float accC[4][4], accH[4][4];
#pragma unroll
            for (int a = 0; a < 4; a++)
#pragma unroll
                for (int b = 0; b < 4; b++) { accC[a][b] = 0.f; accH[a][b] = 0.f; }
#pragma unroll
            for (int ks = 0; ks < 4; ks++) {
                uint4 a = ldm(smb + bb + OF_AGH + aoff + ks * 32);
                MM4(accC, a, SM_CONV);
                MM4(accC, a, SM_CONV + 8192);
                a = ldm(smb + bb + OF_AGL + aoff + ks * 32);
                MM4(accC, a, SM_CONV);
                a = ldm(smb + bb + OF_HH + aoff + ks * 32);
                MM4(accC, a, SM_CONV + 16384);
                MM4(accC, a, SM_CONV + 24576);
                MM4(accH, a, SM_GRU + 81920);
                MM4(accH, a, SM_GRU + 90112);
                a = ldm(smb + bb + OF_HL + aoff + ks * 32);
                MM4(accC, a, SM_CONV + 16384);
                MM4(accH, a, SM_GRU + 81920);
            }
            BAR_SYNC(5, 256);                // agg reads done before m overwrite

            // ---- epilogue 1: m = relu(conv + brel) -> overwrite agg tiles ----
#pragma unroll
            for (int j = 0; j < 4; j++) {
                int c = nh * 32 + j * 8 + 2 * s;
                u32 off = bb + (u32)((mt * 16 + g) * 144 + c * 2);
                u32 hi, lo;
                float m0 = fmaxf(accC[j][0] + sbrel[c], 0.f);
                float m1 = fmaxf(accC[j][1] + sbrel[c + 1], 0.f);
                split2(m0, m1, hi, lo);
                *(u32*)(sm + OF_AGH + off) = hi;
                *(u32*)(sm + OF_AGL + off) = lo;
                m0 = fmaxf(accC[j][2] + sbrel[c], 0.f);
                m1 = fmaxf(accC[j][3] + sbrel[c + 1], 0.f);
                split2(m0, m1, hi, lo);
                *(u32*)(sm + OF_AGH + off + 8 * 144) = hi;
                *(u32*)(sm + OF_AGL + off + 8 * 144) = lo;
            }
            BAR_SYNC(5, 256);                // m visible before loop B

            // ---- Loop B: rz + in GEMMs ----
            float accRZ[8][4], accI[4][4];
#pragma unroll
            for (int a = 0; a < 8; a++)
#pragma unroll
                for (int b = 0; b < 4; b++) accRZ[a][b] = 0.f;
#pragma unroll
            for (int a = 0; a < 4; a++)
#pragma unroll
                for (int b = 0; b < 4; b++) accI[a][b] = 0.f;
#pragma unroll
            for (int ks = 0; ks < 4; ks++) {
                uint4 a = ldm(smb + bb + OF_AGH + aoff + ks * 32);
                MMRZ(a, SM_GRU);
                MMRZ(a, SM_GRU + 16384);
                MM4(accI, a, SM_GRU + 65536);
                MM4(accI, a, SM_GRU + 73728);
                a = ldm(smb + bb + OF_AGL + aoff + ks * 32);
                MMRZ(a, SM_GRU);
                MM4(accI, a, SM_GRU + 65536);
                a = ldm(smb + bb + OF_HH + aoff + ks * 32);
                MMRZ(a, SM_GRU + 32768);
                MMRZ(a, SM_GRU + 49152);
                a = ldm(smb + bb + OF_HL + aoff + ks * 32);
                MMRZ(a, SM_GRU + 32768);
            }
            BAR_ARRIVE(3 + p, 512);          // buffer free (all smem reads done)

            // ---- epilogue 2: gates + blend + store ----
#pragma unroll
            for (int j = 0; j < 4; j++) {
                int c = nh * 32 + j * 8 + 2 * s;
#pragma unroll
                for (int q = 0; q < 2; q++) {
                    int row = mt * 16 + g + q * 8;
                    int gn = n0 + row;
                    if (gn < Nn) {
                        float r0v = sigm(accRZ[j][2 * q]     + sbih[c]     + sbhh[c]);
                        float r1v = sigm(accRZ[j][2 * q + 1] + sbih[c + 1] + sbhh[c + 1]);
                        float z0v = sigm(accRZ[4 + j][2 * q]     + sbih[64 + c]     + sbhh[64 + c]);
                        float z1v = sigm(accRZ[4 + j][2 * q + 1] + sbih[64 + c + 1] + sbhh[64 + c + 1]);
                        float nn0 = tanh_f(accI[j][2 * q]     + sbih[128 + c]     + r0v * (accH[j][2 * q]     + sbhh[128 + c]));
                        float nn1 = tanh_f(accI[j][2 * q + 1] + sbih[128 + c + 1] + r1v * (accH[j][2 * q + 1] + sbhh[128 + c + 1]));
                        float2 hp = *(const float2*)(in_state + gn * 64 + c);
                        float o0 = (1.f - z0v) * nn0 + z0v * hp.x;
                        float o1 = (1.f - z1v) * nn1 + z1v * hp.y;
                        *(float2*)(out_state + gn * 64 + c) = make_float2(o0, o1);
                    }
                }
            }
        }
    }
}

// ---------------- global mean pool ----------------
__global__ void k_pool(const float* __restrict__ feats, float* __restrict__ out) {
    int g = blockIdx.x, f = blockIdx.y, d = threadIdx.x;  // blockDim = 64
    int s = g_gstart[g], e = g_gstart[g + 1];
    const float* base = feats + f * Nn * Dd;
    float s0 = 0.f, s1 = 0.f, s2 = 0.f, s3 = 0.f;
    int i = s;
    for (; i + 3 < e; i += 4) {
        s0 += base[i * Dd + d];
        s1 += base[(i + 1) * Dd + d];
        s2 += base[(i + 2) * Dd + d];
        s3 += base[(i + 3) * Dd + d];
    }
    for (; i < e; i++) s0 += base[i * Dd + d];
    float sum = (s0 + s1) + (s2 + s3);
    int cnt = e - s;
    if (cnt < 1) cnt = 1;
    out[(f * Gg + g) * Dd + d] = sum / (float)cnt;
}

// ---------------- host ----------------
extern "C" void kernel_launch(void* const* d_in, const int* in_sizes, int n_in,
                              void* d_out, int out_size) {
    const float* x     = (const float*)d_in[0];
    const int*   ei    = (const int*)d_in[1];
    const float* att   = (const float*)d_in[2];
    const int*   batch = (const int*)d_in[3];
    const float* lin_W = (const float*)d_in[4];
    const float* lin_b = (const float*)d_in[5];
    const float* Wrel  = (const float*)d_in[6];
    const float* brel  = (const float*)d_in[7];
    const float* Wroot = (const float*)d_in[8];
    const float* Wih   = (const float*)d_in[9];
    const float* Whh   = (const float*)d_in[10];
    const float* bih   = (const float*)d_in[11];
    const float* bhh   = (const float*)d_in[12];

    float* out = (float*)d_out;
    float* feats = out + NFf * Gg * Dd;
    const int* srcp = ei;
    const int* dstp = ei + Ee;

    int sm = 148;
    cudaDeviceGetAttribute(&sm, cudaDevAttrMultiProcessorCount, 0);
    int grid = (sm / 4) * 4;
    if (grid < 4) grid = 4;

    cudaFuncSetAttribute(k_layer, cudaFuncAttributeMaxDynamicSharedMemorySize, LAYER_SHM);
    cudaFuncSetAttribute(k_lin, cudaFuncAttributeMaxDynamicSharedMemorySize, LIN_SHM);

    void *pa, *pb;
    cudaGetSymbolAddress(&pa, g_stateA);
    cudaGetSymbolAddress(&pb, g_stateB);
    float* A = (float*)pa;
    float* B = (float*)pb;

    const int NB = (Nn + 1023) / 1024;

    k_zero<<<(Nn + 255) / 256, 256>>>();
    k_hist<<<(Ee + 255) / 256, 256>>>(dstp, batch);
    k_scan1<<<NB, 1024>>>();
    k_scan2<<<1, 32>>>(NB);
    k_scan3<<<NB, 1024>>>();
    k_scatter<<<(Ee + 255) / 256, 256>>>(srcp, dstp);
    k_sortseg<<<(Nn + 127) / 128, 128>>>();
    k_buildw<<<(Ee + 255) / 256, 256>>>(att);
    k_gscan<<<1, 32>>>();
    k_pack<<<(98304 + 255) / 256, 256>>>(Wrel, Wroot, Wih, Whh);

    k_lin<<<grid, 512, LIN_SHM>>>(x, lin_W, lin_b, A);
    k_layer<<<grid, 512, LAYER_SHM>>>(A, B, 0, brel, bih, bhh);
    k_layer<<<grid, 512, LAYER_SHM>>>(B, A, 1, brel, bih, bhh);
    k_layer<<<grid, 512, LAYER_SHM>>>(A, feats, 2, brel, bih, bhh);
    k_pool<<<dim3(Gg, NFf), 64>>>(feats, out);
}

// round 17
// speedup vs baseline: 1.3067x; 1.0558x over previous
#include <cuda_runtime.h>
#include <cuda_fp16.h>
#include <math.h>

typedef unsigned long long u64;
typedef unsigned int u32;

#define Nn 100000
#define Ee 1600000
#define Ff 128
#define NFf 4
#define Dd 64
#define NLl 3
#define Gg 128
#define NTILE 782    // ceil(Nn/128) for k_lin
#define NT64 1563    // ceil(Nn/64) for k_layer

// ---------------- device scratch (no allocations allowed) ----------------
__device__ int   g_deg[Nn];
__device__ int   g_rowptr[Nn + 1];
__device__ int   g_fill[Nn];
__device__ int   g_bsums[256];
__device__ int   g_srcs[Ee];
__device__ int   g_eids[Ee];
__device__ float g_wcsr[NFf * Ee];
__device__ float g_stateA[NFf * Nn * Dd];
__device__ float g_stateB[NFf * Nn * Dd];
__device__ int   g_gcnt[Gg];
__device__ int   g_gstart[Gg + 1];
// fragment-packed fp16 weights (uint2 per lane-fragment)
__device__ uint2 g_pkconv[12 * 2048];   // [wl][mat: rel,root][ks4][nt8][lane32]
__device__ uint2 g_pkgru[4 * 6144];     // [f][ih2048, hh2048, in1024, hn1024]

// ---------------- helpers ----------------
__device__ __forceinline__ u64 ffma2(u64 a, u64 b, u64 c) {
    u64 d; asm("fma.rn.f32x2 %0,%1,%2,%3;" : "=l"(d) : "l"(a), "l"(b), "l"(c)); return d;
}
__device__ __forceinline__ u64 splat2(float v) {
    u64 d; u32 r = __float_as_uint(v);
    asm("mov.b64 %0,{%1,%2};" : "=l"(d) : "r"(r), "r"(r)); return d;
}
__device__ __forceinline__ float2 unpk(u64 v) {
    u32 lo, hi; asm("mov.b64 {%0,%1},%2;" : "=r"(lo), "=r"(hi) : "l"(v));
    return make_float2(__uint_as_float(lo), __uint_as_float(hi));
}
__device__ __forceinline__ float sigm(float v) { return 1.f / (1.f + __expf(-v)); }
__device__ __forceinline__ float tanh_f(float v) { return 2.f / (1.f + __expf(-2.f * v)) - 1.f; }

__device__ __forceinline__ u32 smem_u32(const void* p) {
    u32 a;
    asm("{ .reg .u64 t; cvta.to.shared.u64 t, %1; cvt.u32.u64 %0, t; }" : "=r"(a) : "l"(p));
    return a;
}

// split (a0,a1) fp32 -> hi fp16x2 word + lo residual fp16x2 word
__device__ __forceinline__ void split2(float a0, float a1, u32& hi, u32& lo) {
    __half h0 = __float2half_rn(a0), h1 = __float2half_rn(a1);
    __half2 hp = __halves2half2(h0, h1);
    float r0 = a0 - __half2float(h0);
    float r1 = a1 - __half2float(h1);
    __half2 lp = __floats2half2_rn(r0, r1);
    hi = *(u32*)&hp; lo = *(u32*)&lp;
}

__device__ __forceinline__ u32 pkh(float a, float b) {
    __half2 p = __floats2half2_rn(a, b);
    return *(u32*)&p;
}

__device__ __forceinline__ uint4 ldm(u32 addr) {
    uint4 r;
    asm volatile("ldmatrix.sync.aligned.m8n8.x4.shared.b16 {%0,%1,%2,%3}, [%4];"
        : "=r"(r.x), "=r"(r.y), "=r"(r.z), "=r"(r.w) : "r"(addr));
    return r;
}
__device__ __forceinline__ void mmaf(float d[4], uint4 a, uint2 b) {
    asm volatile("mma.sync.aligned.m16n8k16.row.col.f32.f16.f16.f32 "
        "{%0,%1,%2,%3}, {%4,%5,%6,%7}, {%8,%9}, {%0,%1,%2,%3};"
        : "+f"(d[0]), "+f"(d[1]), "+f"(d[2]), "+f"(d[3])
        : "r"(a.x), "r"(a.y), "r"(a.z), "r"(a.w), "r"(b.x), "r"(b.y));
}

#define BAR_SYNC(id, cnt)   asm volatile("bar.sync %0, %1;"   :: "r"(id), "r"(cnt) : "memory")
#define BAR_ARRIVE(id, cnt) asm volatile("bar.arrive %0, %1;" :: "r"(id), "r"(cnt) : "memory")

// ---------------- CSR build ----------------
__global__ void k_zero() {
    int i = blockIdx.x * blockDim.x + threadIdx.x;
    if (i < Nn) g_deg[i] = 0;
    if (i < Gg) g_gcnt[i] = 0;
}

__global__ void k_hist(const int* __restrict__ dst, const int* __restrict__ batch) {
    int i = blockIdx.x * blockDim.x + threadIdx.x;
    if (i < Ee) atomicAdd(&g_deg[dst[i]], 1);
    if (i < Nn) atomicAdd(&g_gcnt[batch[i]], 1);
}

__global__ void k_scan1() {
    __shared__ int tmp[1024];
    int i = blockIdx.x * 1024 + threadIdx.x;
    int v = (i < Nn) ? g_deg[i] : 0;
    tmp[threadIdx.x] = v;
    __syncthreads();
    for (int off = 1; off < 1024; off <<= 1) {
        int t = 0;
        if (threadIdx.x >= off) t = tmp[threadIdx.x - off];
        __syncthreads();
        if (threadIdx.x >= off) tmp[threadIdx.x] += t;
        __syncthreads();
    }
    if (i < Nn) g_rowptr[i + 1] = tmp[threadIdx.x];
    if (threadIdx.x == 1023) g_bsums[blockIdx.x] = tmp[1023];
}

__global__ void k_scan2(int nb) {
    if (threadIdx.x == 0 && blockIdx.x == 0) {
        int run = 0;
        for (int b = 0; b < nb; b++) { int v = g_bsums[b]; g_bsums[b] = run; run += v; }
    }
}

__global__ void k_scan3() {
    int i = blockIdx.x * 1024 + threadIdx.x;
    if (i < Nn) {
        int v = g_rowptr[i + 1] + g_bsums[blockIdx.x];
        g_rowptr[i + 1] = v;
        if (i + 1 < Nn) g_fill[i + 1] = v;
    }
    if (i == 0) { g_rowptr[0] = 0; g_fill[0] = 0; }
}

__global__ void k_scatter(const int* __restrict__ src, const int* __restrict__ dst) {
    int e = blockIdx.x * blockDim.x + threadIdx.x;
    if (e < Ee) {
        int d = dst[e];
        int p = atomicAdd(&g_fill[d], 1);
        g_srcs[p] = src[e];
        g_eids[p] = e;
    }
}

__global__ void k_sortseg() {
    int n = blockIdx.x * blockDim.x + threadIdx.x;
    if (n >= Nn) return;
    int b = g_rowptr[n], e = g_rowptr[n + 1];
    for (int i = b + 1; i < e; i++) {
        int ke = g_eids[i], ks = g_srcs[i];
        int j = i - 1;
        while (j >= b && g_eids[j] > ke) {
            g_eids[j + 1] = g_eids[j];
            g_srcs[j + 1] = g_srcs[j];
            j--;
        }
        g_eids[j + 1] = ke;
        g_srcs[j + 1] = ks;
    }
}

__global__ void k_buildw(const float* __restrict__ att) {
    int j = blockIdx.x * blockDim.x + threadIdx.x;
    if (j < Ee) {
        int e = g_eids[j];
#pragma unroll
        for (int f = 0; f < NFf; f++) g_wcsr[f * Ee + j] = att[f * Ee + e];
    }
}

__global__ void k_gscan() {
    if (threadIdx.x == 0 && blockIdx.x == 0) {
        int run = 0;
        for (int g = 0; g < Gg; g++) { g_gstart[g] = run; run += g_gcnt[g]; }
        g_gstart[Gg] = run;
    }
}

// ---------------- weight pre-pack: fp16 fragments (single copy) ----------------
__global__ void k_pack(const float* __restrict__ Wrel, const float* __restrict__ Wroot,
                       const float* __restrict__ Wih, const float* __restrict__ Whh) {
    int i = blockIdx.x * blockDim.x + threadIdx.x;
    if (i >= 49152) return;
    float v00, v01, v10, v11;
    uint2* dst;
    if (i < 24576) {
        int wl = i >> 11;
        int r = i & 2047;
        int mat = r >> 10;          // 0 rel, 1 root
        int fr = r & 1023;
        int ks = fr >> 8, nt = (fr >> 5) & 7, lane = fr & 31;
        int s = lane & 3, n = nt * 8 + (lane >> 2);
        int k0 = ks * 16 + 2 * s;
        const float* Wm = (mat ? Wroot : Wrel) + wl * 4096;   // B[k][n] = W[k*64+n]
        v00 = Wm[k0 * 64 + n];       v01 = Wm[(k0 + 1) * 64 + n];
        v10 = Wm[(k0 + 8) * 64 + n]; v11 = Wm[(k0 + 9) * 64 + n];
        dst = g_pkconv + i;
    } else {
        int j = i - 24576;
        int f = j / 6144;
        int r = j % 6144;
        const float* WI = Wih + f * 12288;
        const float* WH = Whh + f * 12288;
        if (r < 4096) {             // rz: ih, hh (2048 uint2 each)
            int mat = r >> 11;
            int fr = r & 2047;
            int ks = fr >> 9, nt = (fr >> 5) & 15, lane = fr & 31;
            int s = lane & 3, n = nt * 8 + (lane >> 2);
            int k0 = ks * 16 + 2 * s;
            const float* Wm = mat ? WH : WI;                  // B[k][n] = W[n*64+k]
            v00 = Wm[n * 64 + k0];     v01 = Wm[n * 64 + k0 + 1];
            v10 = Wm[n * 64 + k0 + 8]; v11 = Wm[n * 64 + k0 + 9];
        } else {                    // n gate: in, hn (1024 uint2 each)
            int rn = r - 4096;
            int mat = rn >> 10;
            int fr = rn & 1023;
            int ks = fr >> 8, nt = (fr >> 5) & 7, lane = fr & 31;
            int s = lane & 3, n = nt * 8 + (lane >> 2);
            int k0 = ks * 16 + 2 * s;
            const float* Wm = mat ? WH : WI;                  // B[k][n] = W[(128+n)*64+k]
            v00 = Wm[(128 + n) * 64 + k0];     v01 = Wm[(128 + n) * 64 + k0 + 1];
            v10 = Wm[(128 + n) * 64 + k0 + 8]; v11 = Wm[(128 + n) * 64 + k0 + 9];
        }
        dst = g_pkgru + j;
    }
    *dst = make_uint2(pkh(v00, v01), pkh(v10, v11));
}

// ---------------- lin (FFMA champion, unchanged) ----------------
#define LIN_SHM ((8192 + 64 + 16 * 1280) * 4)
__global__ __launch_bounds__(512, 1) void k_lin(const float* __restrict__ x,
                                                const float* __restrict__ W_all,
                                                const float* __restrict__ b_all,
                                                float* __restrict__ out_base) {
    extern __shared__ float sh[];
    float* sW = sh;
    float* sb = sW + 8192;
    float* sX = sb + 64;
    int f = blockIdx.x & 3;
    int fslot = blockIdx.x >> 2;
    int nslot = gridDim.x >> 2;
    const float* W = W_all + f * Ff * Dd;
    const float* b = b_all + f * Dd;
    float* out = out_base + f * Nn * Dd;

    int tid = threadIdx.x;
    for (int i = tid; i < 8192; i += 512) sW[i] = W[i];
    if (tid < 64) sb[tid] = b[tid];
    __syncthreads();
    int warp = tid >> 5, lane = tid & 31;
    int d0 = 2 * lane;
    int nt = lane >> 2, cg = lane & 3;
    float* sXw = sX + warp * 1280;
    float bc0 = sb[d0], bc1 = sb[d0 + 1];

    for (int t = fslot; t < NTILE; t += nslot) {
        int n0 = t * 128 + warp * 8;
        if (n0 >= Nn) continue;
        {
            int n = n0 + nt;
            bool v = n < Nn;
            const float4* xr = (const float4*)(x + (v ? n : 0) * Ff) + cg * 8;
#pragma unroll
            for (int q = 0; q < 8; q++) {
                float4 tv = v ? xr[q] : make_float4(0, 0, 0, 0);
                int c = cg * 32 + q * 4;
                sXw[(c + 0) * 10 + nt] = tv.x;
                sXw[(c + 1) * 10 + nt] = tv.y;
                sXw[(c + 2) * 10 + nt] = tv.z;
                sXw[(c + 3) * 10 + nt] = tv.w;
            }
        }
        __syncwarp();
        u64 acc[4][2];
#pragma unroll
        for (int p = 0; p < 4; p++) { acc[p][0] = 0ull; acc[p][1] = 0ull; }
#pragma unroll 4
        for (int k = 0; k < Ff; k++) {
            float2 w = *(const float2*)(sW + k * 64 + d0);
            u64 sw0 = splat2(w.x), sw1 = splat2(w.y);
            const u64* xp = (const u64*)(sXw + k * 10);
#pragma unroll
            for (int p = 0; p < 4; p++) {
                u64 xv = xp[p];
                acc[p][0] = ffma2(xv, sw0, acc[p][0]);
                acc[p][1] = ffma2(xv, sw1, acc[p][1]);
            }
        }
#pragma unroll
        for (int p = 0; p < 4; p++) {
            float2 a0 = unpk(acc[p][0]), a1 = unpk(acc[p][1]);
            int na = n0 + 2 * p, nb = na + 1;
            if (na < Nn) *(float2*)(out + na * 64 + d0) = make_float2(a0.x + bc0, a1.x + bc1);
            if (nb < Nn) *(float2*)(out + nb * 64 + d0) = make_float2(a0.y + bc0, a1.y + bc1);
        }
        __syncwarp();
    }
}

// ---------------- fused layer: warp-specialized, fp16 2-product split ----------------
#define BUF_SZ  36864
#define OF_AGH  0
#define OF_AGL  9216
#define OF_HH   18432
#define OF_HL   27648
#define SM_CONV 73728        // rel 8K, root 8K
#define SM_GRU  90112        // ih 16K, hh 16K, in 8K, hn 8K
#define SM_BREL 139264
#define SM_BIH  139520
#define SM_BHH  140288
#define LAYER_SHM 141056

#define MM4(ACC, A, BOFF) do { \
    const uint2* _b = (const uint2*)(sm + (BOFF)); \
    _Pragma("unroll") \
    for (int j = 0; j < 4; j++) \
        mmaf(ACC[j], A, _b[(ks * 8 + nh * 4 + j) * 32 + lane]); \
} while (0)

#define MMRZ(A, BOFF) do { \
    const uint2* _b = (const uint2*)(sm + (BOFF)); \
    _Pragma("unroll") \
    for (int j = 0; j < 4; j++) \
        mmaf(accRZ[j], A, _b[(ks * 16 + nh * 4 + j) * 32 + lane]); \
    _Pragma("unroll") \
    for (int j = 0; j < 4; j++) \
        mmaf(accRZ[4 + j], A, _b[(ks * 16 + 8 + nh * 4 + j) * 32 + lane]); \
} while (0)

__global__ __launch_bounds__(512, 1) void k_layer(const float* __restrict__ in_base,
                                                  float* __restrict__ out_base,
                                                  int layer,
                                                  const float* __restrict__ brel_all,
                                                  const float* __restrict__ bih_all,
                                                  const float* __restrict__ bhh_all) {
    extern __shared__ unsigned char sm[];
    u32 smb = smem_u32(sm);
    int tid = threadIdx.x, warp = tid >> 5, lane = tid & 31;
    int f = blockIdx.x & 3;
    int fslot = blockIdx.x >> 2;
    int nslot = gridDim.x >> 2;
    int wl = f * NLl + layer;
    const float* in_state = in_base + f * Nn * Dd;
    float* out_state = out_base + f * Nn * Dd;
    const float* wfp = g_wcsr + f * Ee;

    {   // weights + biases -> smem (all 512 threads)
        const uint4* pc = (const uint4*)(g_pkconv + wl * 2048);
        uint4* dc = (uint4*)(sm + SM_CONV);
        for (int i = tid; i < 1024; i += 512) dc[i] = pc[i];
        const uint4* pg = (const uint4*)(g_pkgru + f * 6144);
        uint4* dg = (uint4*)(sm + SM_GRU);
        for (int i = tid; i < 3072; i += 512) dg[i] = pg[i];
        float* sb = (float*)(sm + SM_BREL);
        if (tid < 64) sb[tid] = brel_all[wl * 64 + tid];
        float* si = (float*)(sm + SM_BIH);
        float* shh = (float*)(sm + SM_BHH);
        if (tid < 192) { si[tid] = bih_all[f * 192 + tid]; shh[tid] = bhh_all[f * 192 + tid]; }
    }
    __syncthreads();

    if (warp >= 8) {
        // ================= PRODUCER (warps 8..15) =================
        int ptid = tid - 256;
        int nl = ptid >> 2, cg = ptid & 3;
        int i = 0;
        for (int t = fslot; t < NT64; t += nslot, i++) {
            int p = i & 1;
            u32 bb = (u32)(p * BUF_SZ);
            BAR_SYNC(3 + p, 512);            // wait buffer empty
            int gn = t * 64 + nl;
            bool v = gn < Nn;
            float hv[16], acc[16];
            const float4* hr = (const float4*)(in_state + (v ? gn : 0) * 64 + cg * 16);
#pragma unroll
            for (int q = 0; q < 4; q++) {
                float4 tv = v ? hr[q] : make_float4(0, 0, 0, 0);
                hv[4 * q] = tv.x; hv[4 * q + 1] = tv.y; hv[4 * q + 2] = tv.z; hv[4 * q + 3] = tv.w;
            }
#pragma unroll
            for (int ii = 0; ii < 16; ii++) acc[ii] = 0.f;
            if (v) {
                int beg = g_rowptr[gn], end = g_rowptr[gn + 1];
                for (int j = beg; j < end; j++) {
                    int sn = g_srcs[j];
                    float w = wfp[j];
                    const float4* sr = (const float4*)(in_state + sn * 64 + cg * 16);
#pragma unroll
                    for (int q = 0; q < 4; q++) {
                        float4 tv = sr[q];
                        acc[4 * q] += w * tv.x; acc[4 * q + 1] += w * tv.y;
                        acc[4 * q + 2] += w * tv.z; acc[4 * q + 3] += w * tv.w;
                    }
                }
            }
#pragma unroll
            for (int ii = 0; ii < 8; ii++) {
                int c = cg * 16 + 2 * ii;
                u32 off = bb + (u32)(nl * 144 + c * 2);
                u32 hi, lo;
                split2(acc[2 * ii], acc[2 * ii + 1], hi, lo);
                *(u32*)(sm + OF_AGH + off) = hi;
                *(u32*)(sm + OF_AGL + off) = lo;
                split2(hv[2 * ii], hv[2 * ii + 1], hi, lo);
                *(u32*)(sm + OF_HH + off) = hi;
                *(u32*)(sm + OF_HL + off) = lo;
            }
            BAR_ARRIVE(1 + p, 512);          // signal buffer full
        }
    } else {
        // ================= CONSUMER (warps 0..7) =================
        int mt = warp >> 1, nh = warp & 1;
        int g = lane >> 2, s = lane & 3;
        u32 aoff = (u32)((mt * 16 + (lane & 15)) * 144 + (lane >> 4) * 16);
        const float* sbrel = (const float*)(sm + SM_BREL);
        const float* sbih  = (const float*)(sm + SM_BIH);
        const float* sbhh  = (const float*)(sm + SM_BHH);

        BAR_ARRIVE(3, 512);
        BAR_ARRIVE(4, 512);

        int i = 0;
        for (int t = fslot; t < NT64; t += nslot, i++) {
            int p = i & 1;
            u32 bb = (u32)(p * BUF_SZ);
            int n0 = t * 64;
            BAR_SYNC(1 + p, 512);            // wait buffer full

            // ---- Loop A: conv + hn GEMMs (fp16, 2 products) ----
            float accC[4][4], accH[4][4];
#pragma unroll
            for (int a = 0; a < 4; a++)
#pragma unroll
                for (int b = 0; b < 4; b++) { accC[a][b] = 0.f; accH[a][b] = 0.f; }
#pragma unroll
            for (int ks = 0; ks < 4; ks++) {
                uint4 a = ldm(smb + bb + OF_AGH + aoff + ks * 32);
                MM4(accC, a, SM_CONV);              // agg(hi) @ rel
                a = ldm(smb + bb + OF_AGL + aoff + ks * 32);
                MM4(accC, a, SM_CONV);              // agg(lo) @ rel
                a = ldm(smb + bb + OF_HH + aoff + ks * 32);
                MM4(accC, a, SM_CONV + 8192);       // h(hi) @ root
                MM4(accH, a, SM_GRU + 40960);       // h(hi) @ hn
                a = ldm(smb + bb + OF_HL + aoff + ks * 32);
                MM4(accC, a, SM_CONV + 8192);       // h(lo) @ root
                MM4(accH, a, SM_GRU + 40960);       // h(lo) @ hn
            }
            BAR_SYNC(5, 256);                // agg reads done before m overwrite

            // ---- epilogue 1: m = relu(conv + brel) -> overwrite agg tiles ----
#pragma unroll
            for (int j = 0; j < 4; j++) {
                int c = nh * 32 + j * 8 + 2 * s;
                u32 off = bb + (u32)((mt * 16 + g) * 144 + c * 2);
                u32 hi, lo;
                float m0 = fmaxf(accC[j][0] + sbrel[c], 0.f);
                float m1 = fmaxf(accC[j][1] + sbrel[c + 1], 0.f);
                split2(m0, m1, hi, lo);
                *(u32*)(sm + OF_AGH + off) = hi;
                *(u32*)(sm + OF_AGL + off) = lo;
                m0 = fmaxf(accC[j][2] + sbrel[c], 0.f);
                m1 = fmaxf(accC[j][3] + sbrel[c + 1], 0.f);
                split2(m0, m1, hi, lo);
                *(u32*)(sm + OF_AGH + off + 8 * 144) = hi;
                *(u32*)(sm + OF_AGL + off + 8 * 144) = lo;
            }
            BAR_SYNC(5, 256);                // m visible before loop B

            // ---- Loop B: rz + in GEMMs (fp16, 2 products) ----
            float accRZ[8][4], accI[4][4];
#pragma unroll
            for (int a = 0; a < 8; a++)
#pragma unroll
                for (int b = 0; b < 4; b++) accRZ[a][b] = 0.f;
#pragma unroll
            for (int a = 0; a < 4; a++)
#pragma unroll
                for (int b = 0; b < 4; b++) accI[a][b] = 0.f;
#pragma unroll
            for (int ks = 0; ks < 4; ks++) {
                uint4 a = ldm(smb + bb + OF_AGH + aoff + ks * 32);
                MMRZ(a, SM_GRU);                    // m(hi) @ ih
                MM4(accI, a, SM_GRU + 32768);       // m(hi) @ in
                a = ldm(smb + bb + OF_AGL + aoff + ks * 32);
                MMRZ(a, SM_GRU);                    // m(lo) @ ih
                MM4(accI, a, SM_GRU + 32768);       // m(lo) @ in
                a = ldm(smb + bb + OF_HH + aoff + ks * 32);
                MMRZ(a, SM_GRU + 16384);            // h(hi) @ hh
                a = ldm(smb + bb + OF_HL + aoff + ks * 32);
                MMRZ(a, SM_GRU + 16384);            // h(lo) @ hh
            }
            BAR_ARRIVE(3 + p, 512);          // buffer free

            // ---- epilogue 2: gates + blend + store ----
#pragma unroll
            for (int j = 0; j < 4; j++) {
                int c = nh * 32 + j * 8 + 2 * s;
#pragma unroll
                for (int q = 0; q < 2; q++) {
                    int row = mt * 16 + g + q * 8;
                    int gn = n0 + row;
                    if (gn < Nn) {
                        float r0v = sigm(accRZ[j][2 * q]     + sbih[c]     + sbhh[c]);
                        float r1v = sigm(accRZ[j][2 * q + 1] + sbih[c + 1] + sbhh[c + 1]);
                        float z0v = sigm(accRZ[4 + j][2 * q]     + sbih[64 + c]     + sbhh[64 + c]);
                        float z1v = sigm(accRZ[4 + j][2 * q + 1] + sbih[64 + c + 1] + sbhh[64 + c + 1]);
                        float nn0 = tanh_f(accI[j][2 * q]     + sbih[128 + c]     + r0v * (accH[j][2 * q]     + sbhh[128 + c]));
                        float nn1 = tanh_f(accI[j][2 * q + 1] + sbih[128 + c + 1] + r1v * (accH[j][2 * q + 1] + sbhh[128 + c + 1]));
                        float2 hp = *(const float2*)(in_state + gn * 64 + c);
                        float o0 = (1.f - z0v) * nn0 + z0v * hp.x;
                        float o1 = (1.f - z1v) * nn1 + z1v * hp.y;
                        *(float2*)(out_state + gn * 64 + c) = make_float2(o0, o1);
                    }
                }
            }
        }
    }
}

// ---------------- global mean pool ----------------
__global__ void k_pool(const float* __restrict__ feats, float* __restrict__ out) {
    int g = blockIdx.x, f = blockIdx.y, d = threadIdx.x;  // blockDim = 64
    int s = g_gstart[g], e = g_gstart[g + 1];
    const float* base = feats + f * Nn * Dd;
    float s0 = 0.f, s1 = 0.f, s2 = 0.f, s3 = 0.f;
    int i = s;
    for (; i + 3 < e; i += 4) {
        s0 += base[i * Dd + d];
        s1 += base[(i + 1) * Dd + d];
        s2 += base[(i + 2) * Dd + d];
        s3 += base[(i + 3) * Dd + d];
    }
    for (; i < e; i++) s0 += base[i * Dd + d];
    float sum = (s0 + s1) + (s2 + s3);
    int cnt = e - s;
    if (cnt < 1) cnt = 1;
    out[(f * Gg + g) * Dd + d] = sum / (float)cnt;
}

// ---------------- host ----------------
extern "C" void kernel_launch(void* const* d_in, const int* in_sizes, int n_in,
                              void* d_out, int out_size) {
    const float* x     = (const float*)d_in[0];
    const int*   ei    = (const int*)d_in[1];
    const float* att   = (const float*)d_in[2];
    const int*   batch = (const int*)d_in[3];
    const float* lin_W = (const float*)d_in[4];
    const float* lin_b = (const float*)d_in[5];
    const float* Wrel  = (const float*)d_in[6];
    const float* brel  = (const float*)d_in[7];
    const float* Wroot = (const float*)d_in[8];
    const float* Wih   = (const float*)d_in[9];
    const float* Whh   = (const float*)d_in[10];
    const float* bih   = (const float*)d_in[11];
    const float* bhh   = (const float*)d_in[12];

    float* out = (float*)d_out;
    float* feats = out + NFf * Gg * Dd;
    const int* srcp = ei;
    const int* dstp = ei + Ee;

    int sm = 148;
    cudaDeviceGetAttribute(&sm, cudaDevAttrMultiProcessorCount, 0);
    int grid = (sm / 4) * 4;
    if (grid < 4) grid = 4;

    cudaFuncSetAttribute(k_layer, cudaFuncAttributeMaxDynamicSharedMemorySize, LAYER_SHM);
    cudaFuncSetAttribute(k_lin, cudaFuncAttributeMaxDynamicSharedMemorySize, LIN_SHM);

    void *pa, *pb;
    cudaGetSymbolAddress(&pa, g_stateA);
    cudaGetSymbolAddress(&pb, g_stateB);
    float* A = (float*)pa;
    float* B = (float*)pb;

    const int NB = (Nn + 1023) / 1024;

    k_zero<<<(Nn + 255) / 256, 256>>>();
    k_hist<<<(Ee + 255) / 256, 256>>>(dstp, batch);
    k_scan1<<<NB, 1024>>>();
    k_scan2<<<1, 32>>>(NB);
    k_scan3<<<NB, 1024>>>();
    k_scatter<<<(Ee + 255) / 256, 256>>>(srcp, dstp);
    k_sortseg<<<(Nn + 127) / 128, 128>>>();
    k_buildw<<<(Ee + 255) / 256, 256>>>(att);
    k_gscan<<<1, 32>>>();
    k_pack<<<(49152 + 255) / 256, 256>>>(Wrel, Wroot, Wih, Whh);

    k_lin<<<grid, 512, LIN_SHM>>>(x, lin_W, lin_b, A);
    k_layer<<<grid, 512, LAYER_SHM>>>(A, B, 0, brel, bih, bhh);
    k_layer<<<grid, 512, LAYER_SHM>>>(B, A, 1, brel, bih, bhh);
    k_layer<<<grid, 512, LAYER_SHM>>>(A, feats, 2, brel, bih, bhh);
    k_pool<<<dim3(Gg, NFf), 64>>>(feats, out);
}